// round 15
// baseline (speedup 1.0000x reference)
#include <cuda_runtime.h>
#include <cuda_fp16.h>
#include <math.h>
#include <stdint.h>

#define N_ 4096
#define T_ 4
#define F_ 256
#define H_ 8
#define C_ 16
#define P_ 1024
#define D_ 32
#define NT_ (N_*T_)
#define MAXTILES 67

#define BK 32
#define APAD 40
#define BPAD 40

// k2_mma: BM=128, BN=128 (N-split), 256 threads, 2 CTAs/SM
#define K2BM 128
#define K2NCH (N_/BK)
#define K2_A(s)     ((s) * 10240)               // 128 rows * 80B
#define K2_B(s)     (20480 + (s)*10240)          // 128 rows * 80B
#define K2_RS       40960
#define K2_RQ       41984
#define K2_RINV     43008
#define SMEM_K2     43520

// k_proj_all / k_gemm3: M=64 tile, single-pass fp16
#define GA(s)        ((s) * 5120)
#define GB(s)        (10240 + (s)*20480)
#define GIDX         51200
#define GRED         51456
#define SMEM_G       52736
#define GKCH         (F_/BK)

// ---- scratch (static device globals) ----
__device__ float g_feat[N_*F_];
__device__ float g_recon[NT_*F_];
__device__ float g_edgefea[NT_*F_];
__device__ float g_nodeproj[N_*F_];
__device__ float g_edgeproj[NT_*F_];
__device__ float g_rowsum[NT_];
__device__ float g_rowsumsq[NT_];
__device__ float g_rownorm[NT_];
__device__ int   g_perm[N_];
__device__ int   g_tile_s[MAXTILES];
__device__ int   g_tile_start[MAXTILES];
__device__ int   g_tile_cnt[MAXTILES];
__device__ __align__(16) __half g_fT16[F_*N_];
__device__ __align__(16) __half g_W16[37*F_*F_];

// ---- helpers ----
__device__ __forceinline__ uint32_t smem_u32(const void* p) {
    uint32_t a;
    asm("{ .reg .u64 t; cvta.to.shared.u64 t, %1; cvt.u32.u64 %0, t; }"
        : "=r"(a) : "l"(p));
    return a;
}
__device__ __forceinline__ float4 ldg4(const float* p) {
    float4 v;
    asm volatile("ld.global.nc.v4.f32 {%0,%1,%2,%3}, [%4];"
                 : "=f"(v.x), "=f"(v.y), "=f"(v.z), "=f"(v.w) : "l"(p));
    return v;
}
__device__ __forceinline__ void ldm_x4(uint32_t* r, uint32_t addr) {
    asm volatile("ldmatrix.sync.aligned.m8n8.x4.shared.b16 {%0,%1,%2,%3}, [%4];"
                 : "=r"(r[0]), "=r"(r[1]), "=r"(r[2]), "=r"(r[3]) : "r"(addr));
}
__device__ __forceinline__ void mma_f16(float* d, const uint32_t* a,
                                        uint32_t b0, uint32_t b1) {
    asm volatile("mma.sync.aligned.m16n8k16.row.col.f32.f16.f16.f32 "
                 "{%0,%1,%2,%3}, {%4,%5,%6,%7}, {%8,%9}, {%0,%1,%2,%3};"
                 : "+f"(d[0]), "+f"(d[1]), "+f"(d[2]), "+f"(d[3])
                 : "r"(a[0]), "r"(a[1]), "r"(a[2]), "r"(a[3]), "r"(b0), "r"(b1));
}
__device__ __forceinline__ void cpa16(uint32_t dst, const void* src) {
    asm volatile("cp.async.cg.shared.global [%0], [%1], 16;" :: "r"(dst), "l"(src));
}
#define CP_COMMIT() asm volatile("cp.async.commit_group;" ::: "memory")
#define CP_WAIT0()  asm volatile("cp.async.wait_group 0;"  ::: "memory")

// ls generation + fp16 pack of 16 values (4 float4 pairs) + row stats
__device__ __forceinline__ void pack_ls16(const float4* L, const float4* M,
                                          float& psum, float& psq,
                                          uint32_t* Ah)
{
    #pragma unroll
    for (int q = 0; q < 4; q++) {
        float v0 = fmaxf(L[q].x * M[q].x, 0.f);
        float v1 = fmaxf(L[q].y * M[q].y, 0.f);
        float v2 = fmaxf(L[q].z * M[q].z, 0.f);
        float v3 = fmaxf(L[q].w * M[q].w, 0.f);
        psum += (v0 + v1) + (v2 + v3);
        psq = fmaf(v0, v0, psq); psq = fmaf(v1, v1, psq);
        psq = fmaf(v2, v2, psq); psq = fmaf(v3, v3, psq);
        __half2 h0 = __floats2half2_rn(v0, v1);
        __half2 h1 = __floats2half2_rn(v2, v3);
        Ah[q * 2 + 0] = *(uint32_t*)&h0;
        Ah[q * 2 + 1] = *(uint32_t*)&h1;
    }
}

__device__ __forceinline__ void pack_f16(float4 a, float4 b, uint32_t* Ah)
{
    __half2 h0 = __floats2half2_rn(a.x, a.y);
    __half2 h1 = __floats2half2_rn(a.z, a.w);
    __half2 h2 = __floats2half2_rn(b.x, b.y);
    __half2 h3 = __floats2half2_rn(b.z, b.w);
    Ah[0] = *(uint32_t*)&h0;
    Ah[1] = *(uint32_t*)&h1;
    Ah[2] = *(uint32_t*)&h2;
    Ah[3] = *(uint32_t*)&h3;
}

// ============================================================
// K2-MMA N-split: BM=128, BN=128, 256 threads (8 warps 4m x 2n),
// 2 CTAs/SM. grid = (2 n-halves, 128 nt-tiles); halves adjacent.
// recon = ls @ feat; fused ls gen, rowsum/sq, recon, edge_fea.
// ============================================================
__global__ __launch_bounds__(256, 2) void k2_mma(const float* __restrict__ linear,
                                                 const float* __restrict__ mask)
{
    extern __shared__ char sm[];
    const uint32_t sb = smem_u32(sm);
    const int tid = threadIdx.x;
    const int wid = tid >> 5, lane = tid & 31;
    const int warp_m = wid & 3, warp_n = wid >> 2;   // 4m x 2n
    const int nHalf  = blockIdx.x;                    // 0/1: which 128 cols
    const int ntBase = blockIdx.y * K2BM;

    // A producer: row = tid>>1 (0..127), k-offset = (tid&1)*16
    const int arow = tid >> 1;
    const int akof = (tid & 1) * 16;
    const float* lptr = linear + (size_t)(ntBase + arow) * N_ + akof;
    const float* mptr = mask   + (size_t)(ntBase + arow) * N_ + akof;
    const uint32_t aSt = (uint32_t)(arow * APAD + akof) * 2;

    // B producer: local row = tid>>1 (0..127) of this n-half, 32B halves
    const int brow = tid >> 1;
    const int bhalf = tid & 1;
    const char* bsrc = (const char*)(g_fT16 + (size_t)(nHalf * 128 + brow) * N_) + bhalf * 32;
    const uint32_t bSt = (uint32_t)(brow * BPAD) * 2 + bhalf * 32;

    float psum = 0.f, psq = 0.f;
    uint32_t Ah[8];
    float4 L[4], M4v[4];

    const int aRowL = warp_m * 32 + (lane & 7) + ((lane >> 3) & 1) * 8;
    const int aColL = (lane >> 4) * 8;
    const int bRowL = warp_n * 64 + (lane & 7) + ((lane >> 4) & 1) * 8;
    const int bColL = ((lane >> 3) & 1) * 8;

    // prologue: chunk 0
    #pragma unroll
    for (int q = 0; q < 4; q++) { L[q] = ldg4(lptr + q * 4); M4v[q] = ldg4(mptr + q * 4); }
    {
        uint32_t d = sb + K2_B(0) + bSt;
        cpa16(d, bsrc);
        cpa16(d + 16, bsrc + 16);
    }
    CP_COMMIT();
    pack_ls16(L, M4v, psum, psq, Ah);
    *(uint4*)(sm + K2_A(0) + aSt)      = make_uint4(Ah[0], Ah[1], Ah[2], Ah[3]);
    *(uint4*)(sm + K2_A(0) + aSt + 16) = make_uint4(Ah[4], Ah[5], Ah[6], Ah[7]);
    CP_WAIT0();
    __syncthreads();

    float acc[2][8][4];
    #pragma unroll
    for (int i = 0; i < 2; i++)
        #pragma unroll
        for (int j = 0; j < 8; j++)
            #pragma unroll
            for (int q = 0; q < 4; q++) acc[i][j][q] = 0.f;

    for (int c = 0; c < K2NCH; c++) {
        const int s = c & 1;
        const bool more = (c + 1 < K2NCH);
        if (more) {
            uint32_t d = sb + K2_B(s ^ 1) + bSt;
            const char* src = bsrc + (size_t)(c + 1) * BK * 2;
            cpa16(d, src);
            cpa16(d + 16, src + 16);
            CP_COMMIT();
            const float* lp = lptr + (c + 1) * BK;
            const float* mp = mptr + (c + 1) * BK;
            #pragma unroll
            for (int q = 0; q < 4; q++) { L[q] = ldg4(lp + q * 4); M4v[q] = ldg4(mp + q * 4); }
        }

        const uint32_t aB = sb + K2_A(s);
        const uint32_t bB = sb + K2_B(s);

        #pragma unroll
        for (int ks = 0; ks < BK; ks += 16) {
            uint32_t ah[2][4], bb[4][4];
            ldm_x4(ah[0], aB + (uint32_t)((aRowL)      * APAD + ks + aColL) * 2);
            ldm_x4(ah[1], aB + (uint32_t)((aRowL + 16) * APAD + ks + aColL) * 2);
            #pragma unroll
            for (int g = 0; g < 4; g++)
                ldm_x4(bb[g], bB + (uint32_t)((bRowL + g * 16) * BPAD + ks + bColL) * 2);
            #pragma unroll
            for (int mf = 0; mf < 2; mf++)
                #pragma unroll
                for (int nf = 0; nf < 8; nf++)
                    mma_f16(acc[mf][nf], ah[mf],
                            bb[nf >> 1][(nf & 1) * 2], bb[nf >> 1][(nf & 1) * 2 + 1]);
        }

        if (more) {
            pack_ls16(L, M4v, psum, psq, Ah);
            *(uint4*)(sm + K2_A(s^1) + aSt)      = make_uint4(Ah[0], Ah[1], Ah[2], Ah[3]);
            *(uint4*)(sm + K2_A(s^1) + aSt + 16) = make_uint4(Ah[4], Ah[5], Ah[6], Ah[7]);
            CP_WAIT0();
            __syncthreads();
        }
    }

    // row reductions (2 partials per row)
    ((float*)(sm + K2_RS))[arow * 2 + (tid & 1)] = psum;
    ((float*)(sm + K2_RQ))[arow * 2 + (tid & 1)] = psq;
    __syncthreads();
    if (tid < K2BM) {
        const float* rs = (const float*)(sm + K2_RS) + tid * 2;
        const float* rq = (const float*)(sm + K2_RQ) + tid * 2;
        float ss = rs[0] + rs[1];
        float sq = rq[0] + rq[1];
        g_rowsum[ntBase + tid]   = ss;   // both halves write identical values
        g_rowsumsq[ntBase + tid] = sq;
        ((float*)(sm + K2_RINV))[tid] = 1.f / (ss + 1.f);
    }
    __syncthreads();
    const float* rinv = (const float*)(sm + K2_RINV);

    #pragma unroll
    for (int mf = 0; mf < 2; mf++) {
        #pragma unroll
        for (int half = 0; half < 2; half++) {
            int row = warp_m * 32 + mf * 16 + half * 8 + (lane >> 2);
            int nt = ntBase + row;
            float inv = rinv[row];
            const float* fb = g_feat + (size_t)(nt >> 2) * F_;
            float* rb = g_recon   + (size_t)nt * F_;
            float* eb = g_edgefea + (size_t)nt * F_;
            #pragma unroll
            for (int nf = 0; nf < 8; nf++) {
                int col = nHalf * 128 + warp_n * 64 + nf * 8 + (lane & 3) * 2;
                float d0 = acc[mf][nf][half * 2];
                float d1 = acc[mf][nf][half * 2 + 1];
                *(float2*)(rb + col) = make_float2(d0, d1);
                float2 fv = *(const float2*)(fb + col);
                *(float2*)(eb + col) = make_float2((d0 + fv.x) * inv, (d1 + fv.y) * inv);
            }
        }
    }
}

// ============================================================
// K_proj_all: merged bucketed projections, single-pass fp16.
// ============================================================
__global__ __launch_bounds__(256, 2) void k_proj_all()
{
    extern __shared__ char sm[];
    const uint32_t sb = smem_u32(sm);
    const int tid = threadIdx.x;
    const int wid = tid >> 5, lane = tid & 31;
    const int warp_m = wid & 1, warp_n = wid >> 1;

    const int t = blockIdx.x;
    const int cnt = g_tile_cnt[t];
    if (cnt == 0) return;
    const int s = g_tile_s[t];
    const int y = blockIdx.y;
    int mode, j = 0;
    if (y < 4)       { mode = 0; j = y; }
    else if (y == 4) { mode = 1; }
    else             { mode = 2; j = y - 5; }

    int* sidx = (int*)(sm + GIDX);
    const int start = g_tile_start[t];
    if (tid < 64) sidx[tid] = g_perm[start + min(tid, cnt - 1)];
    __syncthreads();

    const int arow = tid >> 2;
    const int akof = (tid & 3) * 8;
    const float* aptr;
    if (mode == 2) aptr = g_edgefea + ((size_t)sidx[arow] * T_ + j) * F_ + akof;
    else           aptr = g_feat + (size_t)sidx[arow] * F_ + akof;
    const uint32_t aSt = (uint32_t)(arow * APAD + akof) * 2;

    int z;
    if (mode == 0)      z = 1 + s * T_ + j;
    else if (mode == 1) z = 17 + s;
    else                z = 21 + s * T_ + j;
    const char* b_src = (const char*)(g_W16 + (size_t)z * F_ * F_ + (size_t)tid * F_);
    const uint32_t bSt = (uint32_t)(tid * BPAD) * 2;

    const int aRowL = warp_m * 32 + (lane & 7) + ((lane >> 3) & 1) * 8;
    const int aColL = (lane >> 4) * 8;
    const int bRowL = warp_n * 64 + (lane & 7) + ((lane >> 4) & 1) * 8;
    const int bColL = ((lane >> 3) & 1) * 8;

    uint32_t Ah[4];
    float4 Aa, Ab;

    Aa = ldg4(aptr); Ab = ldg4(aptr + 4);
    {
        uint32_t d = sb + GB(0) + bSt;
        #pragma unroll
        for (int q = 0; q < 4; q++) cpa16(d + q * 16, b_src + q * 16);
    }
    CP_COMMIT();
    pack_f16(Aa, Ab, Ah);
    *(uint4*)(sm + GA(0) + aSt) = make_uint4(Ah[0], Ah[1], Ah[2], Ah[3]);
    CP_WAIT0();
    __syncthreads();

    float acc[2][8][4];
    #pragma unroll
    for (int i = 0; i < 2; i++)
        #pragma unroll
        for (int q = 0; q < 8; q++)
            #pragma unroll
            for (int e = 0; e < 4; e++) acc[i][q][e] = 0.f;

    for (int c = 0; c < GKCH; c++) {
        const int st = c & 1;
        const bool more = (c + 1 < GKCH);
        if (more) {
            uint32_t d = sb + GB(st ^ 1) + bSt;
            const char* srcb = b_src + (size_t)(c + 1) * BK * 2;
            #pragma unroll
            for (int q = 0; q < 4; q++) cpa16(d + q * 16, srcb + q * 16);
            CP_COMMIT();
            Aa = ldg4(aptr + (c + 1) * BK);
            Ab = ldg4(aptr + (c + 1) * BK + 4);
        }

        const uint32_t aB = sb + GA(st);
        const uint32_t bB = sb + GB(st);

        #pragma unroll
        for (int ks = 0; ks < BK; ks += 16) {
            uint32_t ah[2][4], bb[4][4];
            ldm_x4(ah[0], aB + (uint32_t)((aRowL)      * APAD + ks + aColL) * 2);
            ldm_x4(ah[1], aB + (uint32_t)((aRowL + 16) * APAD + ks + aColL) * 2);
            #pragma unroll
            for (int g = 0; g < 4; g++)
                ldm_x4(bb[g], bB + (uint32_t)((bRowL + g * 16) * BPAD + ks + bColL) * 2);
            #pragma unroll
            for (int mf = 0; mf < 2; mf++)
                #pragma unroll
                for (int nf = 0; nf < 8; nf++)
                    mma_f16(acc[mf][nf], ah[mf],
                            bb[nf >> 1][(nf & 1) * 2], bb[nf >> 1][(nf & 1) * 2 + 1]);
        }

        if (more) {
            pack_f16(Aa, Ab, Ah);
            *(uint4*)(sm + GA(st^1) + aSt) = make_uint4(Ah[0], Ah[1], Ah[2], Ah[3]);
            CP_WAIT0();
            __syncthreads();
        }
    }

    if (mode == 0) {
        float* sred = (float*)(sm + GRED);
        #pragma unroll
        for (int mf = 0; mf < 2; mf++) {
            #pragma unroll
            for (int half = 0; half < 2; half++) {
                int row = warp_m * 32 + mf * 16 + half * 8 + (lane >> 2);
                int node = sidx[row];
                const float* rr = g_recon + ((size_t)node * T_ + j) * F_;
                float part = 0.f;
                #pragma unroll
                for (int nf = 0; nf < 8; nf++) {
                    int col = warp_n * 64 + nf * 8 + (lane & 3) * 2;
                    float2 rv = *(const float2*)(rr + col);
                    float d0 = acc[mf][nf][half * 2]     - rv.x;
                    float d1 = acc[mf][nf][half * 2 + 1] - rv.y;
                    part = fmaf(d0, d0, part);
                    part = fmaf(d1, d1, part);
                }
                part += __shfl_xor_sync(0xffffffffu, part, 1);
                part += __shfl_xor_sync(0xffffffffu, part, 2);
                if ((lane & 3) == 0) sred[row * 4 + warp_n] = part;
            }
        }
        __syncthreads();
        if (tid < 64) {
            const float* r4 = sred + tid * 4;
            float tot = (r4[0] + r4[1]) + (r4[2] + r4[3]);
            if (tid < cnt)
                g_rownorm[sidx[tid] * T_ + j] = sqrtf(tot);
        }
    } else {
        #pragma unroll
        for (int mf = 0; mf < 2; mf++) {
            #pragma unroll
            for (int half = 0; half < 2; half++) {
                int row = warp_m * 32 + mf * 16 + half * 8 + (lane >> 2);
                if (row >= cnt) continue;
                int node = sidx[row];
                float* ob;
                if (mode == 1) ob = g_nodeproj + (size_t)node * F_;
                else           ob = g_edgeproj + ((size_t)node * T_ + j) * F_;
                #pragma unroll
                for (int nf = 0; nf < 8; nf++) {
                    int col = warp_n * 64 + nf * 8 + (lane & 3) * 2;
                    *(float2*)(ob + col) = make_float2(acc[mf][nf][half * 2],
                                                       acc[mf][nf][half * 2 + 1]);
                }
            }
        }
    }
}

// ============================================================
// K_gemm3: g_feat = feature @ theta^T + bias (single-pass fp16)
// ============================================================
__global__ __launch_bounds__(256, 2) void k_gemm3(const float* __restrict__ Ain,
                                                  const float* __restrict__ bias)
{
    extern __shared__ char sm[];
    const uint32_t sb = smem_u32(sm);
    const int tid = threadIdx.x;
    const int wid = tid >> 5, lane = tid & 31;
    const int warp_m = wid & 1, warp_n = wid >> 1;
    const int mBase = blockIdx.x * 64;

    const int arow = tid >> 2;
    const int akof = (tid & 3) * 8;
    const float* aptr = Ain + (size_t)(mBase + arow) * F_ + akof;
    const uint32_t aSt = (uint32_t)(arow * APAD + akof) * 2;

    const char* b_src = (const char*)(g_W16 + (size_t)tid * F_);
    const uint32_t bSt = (uint32_t)(tid * BPAD) * 2;

    const int aRowL = warp_m * 32 + (lane & 7) + ((lane >> 3) & 1) * 8;
    const int aColL = (lane >> 4) * 8;
    const int bRowL = warp_n * 64 + (lane & 7) + ((lane >> 4) & 1) * 8;
    const int bColL = ((lane >> 3) & 1) * 8;

    uint32_t Ah[4];
    float4 Aa, Ab;

    Aa = ldg4(aptr); Ab = ldg4(aptr + 4);
    {
        uint32_t d = sb + GB(0) + bSt;
        #pragma unroll
        for (int q = 0; q < 4; q++) cpa16(d + q * 16, b_src + q * 16);
    }
    CP_COMMIT();
    pack_f16(Aa, Ab, Ah);
    *(uint4*)(sm + GA(0) + aSt) = make_uint4(Ah[0], Ah[1], Ah[2], Ah[3]);
    CP_WAIT0();
    __syncthreads();

    float acc[2][8][4];
    #pragma unroll
    for (int i = 0; i < 2; i++)
        #pragma unroll
        for (int q = 0; q < 8; q++)
            #pragma unroll
            for (int e = 0; e < 4; e++) acc[i][q][e] = 0.f;

    for (int c = 0; c < GKCH; c++) {
        const int st = c & 1;
        const bool more = (c + 1 < GKCH);
        if (more) {
            uint32_t d = sb + GB(st ^ 1) + bSt;
            const char* srcb = b_src + (size_t)(c + 1) * BK * 2;
            #pragma unroll
            for (int q = 0; q < 4; q++) cpa16(d + q * 16, srcb + q * 16);
            CP_COMMIT();
            Aa = ldg4(aptr + (c + 1) * BK);
            Ab = ldg4(aptr + (c + 1) * BK + 4);
        }

        const uint32_t aB = sb + GA(st);
        const uint32_t bB = sb + GB(st);

        #pragma unroll
        for (int ks = 0; ks < BK; ks += 16) {
            uint32_t ah[2][4], bb[4][4];
            ldm_x4(ah[0], aB + (uint32_t)((aRowL)      * APAD + ks + aColL) * 2);
            ldm_x4(ah[1], aB + (uint32_t)((aRowL + 16) * APAD + ks + aColL) * 2);
            #pragma unroll
            for (int g = 0; g < 4; g++)
                ldm_x4(bb[g], bB + (uint32_t)((bRowL + g * 16) * BPAD + ks + bColL) * 2);
            #pragma unroll
            for (int mf = 0; mf < 2; mf++)
                #pragma unroll
                for (int nf = 0; nf < 8; nf++)
                    mma_f16(acc[mf][nf], ah[mf],
                            bb[nf >> 1][(nf & 1) * 2], bb[nf >> 1][(nf & 1) * 2 + 1]);
        }

        if (more) {
            pack_f16(Aa, Ab, Ah);
            *(uint4*)(sm + GA(st^1) + aSt) = make_uint4(Ah[0], Ah[1], Ah[2], Ah[3]);
            CP_WAIT0();
            __syncthreads();
        }
    }

    #pragma unroll
    for (int mf = 0; mf < 2; mf++) {
        #pragma unroll
        for (int half = 0; half < 2; half++) {
            int row = warp_m * 32 + mf * 16 + half * 8 + (lane >> 2);
            float* ob = g_feat + (size_t)(mBase + row) * F_;
            #pragma unroll
            for (int nf = 0; nf < 8; nf++) {
                int col = warp_n * 64 + nf * 8 + (lane & 3) * 2;
                *(float2*)(ob + col) = make_float2(acc[mf][nf][half * 2] + bias[col],
                                                   acc[mf][nf][half * 2 + 1] + bias[col + 1]);
            }
        }
    }
}

// ============================================================
// K_wconv: weights fp32 -> fp16
// ============================================================
__global__ __launch_bounds__(256) void k_wconv(const float* __restrict__ th,
                                               const float* __restrict__ rp,
                                               const float* __restrict__ np,
                                               const float* __restrict__ ep)
{
    int i4 = blockIdx.x * 256 + threadIdx.x;
    int i = i4 * 4;
    int z = i >> 16;
    int off = i & 65535;
    const float* src;
    if (z == 0)      src = th;
    else if (z < 17) src = rp + (size_t)(z - 1)  * 65536;
    else if (z < 21) src = np + (size_t)(z - 17) * 65536;
    else             src = ep + (size_t)(z - 21) * 65536;
    float4 v = ldg4(src + off);
    __half2 h0 = __floats2half2_rn(v.x, v.y);
    __half2 h1 = __floats2half2_rn(v.z, v.w);
    *(uint2*)(g_W16 + i) = make_uint2(*(uint32_t*)&h0, *(uint32_t*)&h1);
}

// ============================================================
// K_featT: featT fp16 [F_][N_] from g_feat
// ============================================================
__global__ void k_featT()
{
    __shared__ float tile[32][33];
    int x = blockIdx.x * 32 + threadIdx.x;
    int y = blockIdx.y * 32 + threadIdx.y;
    #pragma unroll
    for (int i = 0; i < 32; i += 8)
        tile[threadIdx.y + i][threadIdx.x] = g_feat[(size_t)(y + i) * F_ + x];
    __syncthreads();
    int f2 = blockIdx.x * 32 + threadIdx.y;
    int n2 = blockIdx.y * 32 + threadIdx.x;
    #pragma unroll
    for (int i = 0; i < 32; i += 8) {
        float v = tile[threadIdx.x][threadIdx.y + i];
        g_fT16[(size_t)(f2 + i) * N_ + n2] = __float2half_rn(v);
    }
}

// ============================================================
// K_sort
// ============================================================
__global__ __launch_bounds__(256) void k_sort(const int* __restrict__ nmm)
{
    __shared__ int hist[4][256];
    __shared__ int basep[4][256];
    __shared__ int btot[4];
    __shared__ int boff[4];

    const int tid = threadIdx.x;
    const int r0 = tid * 16;
    int myb[16];
    int c[4] = {0, 0, 0, 0};
    #pragma unroll
    for (int i = 0; i < 16; i++) {
        int b = nmm[r0 + i];
        myb[i] = b;
        c[b]++;
    }
    #pragma unroll
    for (int b = 0; b < 4; b++) hist[b][tid] = c[b];
    __syncthreads();

    const int w = tid >> 5, lane = tid & 31;
    if (w < 4) {
        int b = w;
        int loc[8];
        int sum = 0;
        #pragma unroll
        for (int q = 0; q < 8; q++) {
            loc[q] = sum;
            sum += hist[b][lane * 8 + q];
        }
        int pre = sum;
        #pragma unroll
        for (int off = 1; off < 32; off <<= 1) {
            int v = __shfl_up_sync(0xffffffffu, pre, off);
            if (lane >= off) pre += v;
        }
        int tot = __shfl_sync(0xffffffffu, pre, 31);
        pre -= sum;
        #pragma unroll
        for (int q = 0; q < 8; q++) basep[b][lane * 8 + q] = pre + loc[q];
        if (lane == 31) btot[b] = tot;
    }
    __syncthreads();

    if (tid == 0) {
        int off = 0, t = 0;
        for (int b = 0; b < 4; b++) {
            boff[b] = off;
            int cnt = btot[b];
            for (int k = 0; k < cnt; k += 64) {
                g_tile_s[t] = b;
                g_tile_start[t] = off + k;
                g_tile_cnt[t] = min(64, cnt - k);
                t++;
            }
            off += cnt;
        }
        for (; t < MAXTILES; t++) { g_tile_cnt[t] = 0; g_tile_s[t] = 0; g_tile_start[t] = 0; }
    }
    __syncthreads();

    int pos[4];
    #pragma unroll
    for (int b = 0; b < 4; b++) pos[b] = boff[b] + basep[b][tid];
    #pragma unroll
    for (int i = 0; i < 16; i++) {
        int b = myb[i];
        g_perm[pos[b]++] = r0 + i;
    }
}

// ============================================================
// K_attn
// ============================================================
__global__ __launch_bounds__(256) void k_attn(float* __restrict__ node_rep)
{
    const int i = blockIdx.x, tid = threadIdx.x;
    const int h = tid >> 5, lane = tid & 31;
    __shared__ float sw[T_][H_];

    float np = g_nodeproj[(size_t)i * F_ + tid];
    const float inv = rsqrtf((float)D_);

    #pragma unroll
    for (int t = 0; t < T_; t++) {
        float v = np * g_edgeproj[((size_t)i * T_ + t) * F_ + tid];
        #pragma unroll
        for (int off = 16; off > 0; off >>= 1)
            v += __shfl_down_sync(0xffffffffu, v, off);
        if (lane == 0) sw[t][h] = v * inv;
    }
    __syncthreads();

    if (tid < T_) {
        int t = tid;
        float mx = sw[t][0];
        #pragma unroll
        for (int hh = 1; hh < H_; hh++) mx = fmaxf(mx, sw[t][hh]);
        float sm = 0.f;
        #pragma unroll
        for (int hh = 0; hh < H_; hh++) {
            float e = expf(sw[t][hh] - mx);
            sw[t][hh] = e;
            sm += e;
        }
        float r = 1.f / sm;
        #pragma unroll
        for (int hh = 0; hh < H_; hh++) sw[t][hh] *= r;
    }
    __syncthreads();

    float rep = 0.f;
    #pragma unroll
    for (int t = 0; t < T_; t++)
        rep += fmaxf(sw[t][h] * g_edgefea[((size_t)i * T_ + t) * F_ + tid], 0.f);
    node_rep[(size_t)i * F_ + tid] = rep;
}

// ============================================================
// K_pred
// ============================================================
__global__ __launch_bounds__(256) void k_pred(const float* __restrict__ node_rep,
                                              const int* __restrict__ node_idx,
                                              const float* __restrict__ pw,
                                              const float* __restrict__ pb,
                                              float* __restrict__ predict)
{
    const int warp = threadIdx.x >> 5, lane = threadIdx.x & 31;
    const int p = blockIdx.x * 8 + warp;
    const float* a = node_rep + (size_t)node_idx[p] * F_;

    float part[C_];
    #pragma unroll
    for (int c = 0; c < C_; c++) part[c] = 0.f;
    for (int f = lane; f < F_; f += 32) {
        float av = a[f];
        #pragma unroll
        for (int c = 0; c < C_; c++)
            part[c] = fmaf(av, pw[c * F_ + f], part[c]);
    }
    #pragma unroll
    for (int c = 0; c < C_; c++)
        #pragma unroll
        for (int off = 16; off > 0; off >>= 1)
            part[c] += __shfl_down_sync(0xffffffffu, part[c], off);

    if (lane == 0) {
        float sig[C_];
        float mx = -1e30f;
        #pragma unroll
        for (int c = 0; c < C_; c++) {
            float l = part[c] + pb[c];
            float sg = 1.f / (1.f + expf(-l));
            sig[c] = sg;
            mx = fmaxf(mx, sg);
        }
        float sm = 0.f;
        #pragma unroll
        for (int c = 0; c < C_; c++) {
            float e = expf(sig[c] - mx);
            sig[c] = e;
            sm += e;
        }
        float r = 1.f / sm;
        #pragma unroll
        for (int c = 0; c < C_; c++)
            predict[(size_t)p * C_ + c] = sig[c] * r;
    }
}

// ============================================================
// K_reduce
// ============================================================
__global__ __launch_bounds__(256) void k_reduce(float* __restrict__ lossOut)
{
    __shared__ float s1[256], s2[256], s3[256];
    int tid = threadIdx.x;
    float l1 = 0.f, l2 = 0.f, re = 0.f;
    for (int i = tid; i < NT_; i += 256) {
        l1 += g_rowsum[i];
        l2 += sqrtf(g_rowsumsq[i]);
        re += g_rownorm[i];
    }
    s1[tid] = l1; s2[tid] = l2; s3[tid] = re;
    __syncthreads();
    for (int off = 128; off > 0; off >>= 1) {
        if (tid < off) {
            s1[tid] += s1[tid + off];
            s2[tid] += s2[tid + off];
            s3[tid] += s3[tid + off];
        }
        __syncthreads();
    }
    if (tid == 0)
        lossOut[0] = 0.1f * (0.01f * s3[0] + 0.2f * s2[0] + s1[0]);
}

// ============================================================
extern "C" void kernel_launch(void* const* d_in, const int* in_sizes, int n_in,
                              void* d_out, int out_size)
{
    (void)in_sizes; (void)n_in; (void)out_size;
    const float* feature  = (const float*)d_in[0];
    const float* mask     = (const float*)d_in[1];
    const int*   nmm      = (const int*)  d_in[2];
    const int*   node_idx = (const int*)  d_in[3];
    const float* theta_w  = (const float*)d_in[4];
    const float* theta_b  = (const float*)d_in[5];
    const float* linear   = (const float*)d_in[6];
    const float* rp       = (const float*)d_in[7];
    const float* mhnp     = (const float*)d_in[8];
    const float* mhep     = (const float*)d_in[9];
    const float* pw       = (const float*)d_in[10];
    const float* pb       = (const float*)d_in[11];

    float* out      = (float*)d_out;
    float* predict  = out;
    float* loss     = out + P_ * C_;
    float* node_rep = out + P_ * C_ + 1;

    cudaFuncSetAttribute(k2_mma,     cudaFuncAttributeMaxDynamicSharedMemorySize, SMEM_K2);
    cudaFuncSetAttribute(k_proj_all, cudaFuncAttributeMaxDynamicSharedMemorySize, SMEM_G);
    cudaFuncSetAttribute(k_gemm3,    cudaFuncAttributeMaxDynamicSharedMemorySize, SMEM_G);

    // k2 placed 4th => lands in the profiled slot
    k_wconv<<<37 * 65536 / 1024, 256>>>(theta_w, rp, mhnp, mhep);
    k_gemm3<<<N_ / 64, 256, SMEM_G>>>(feature, theta_b);
    k_featT<<<dim3(8, 128), dim3(32, 8)>>>();
    k2_mma<<<dim3(2, NT_ / K2BM), 256, SMEM_K2>>>(linear, mask);
    k_sort<<<1, 256>>>(nmm);
    k_proj_all<<<dim3(MAXTILES, 9), 256, SMEM_G>>>();
    k_attn<<<N_, 256>>>(node_rep);
    k_pred<<<P_ / 8, 256>>>(node_rep, node_idx, pw, pb, predict);
    k_reduce<<<1, 256>>>(loss);
}

// round 16
// speedup vs baseline: 1.1615x; 1.1615x over previous
#include <cuda_runtime.h>
#include <cuda_fp16.h>
#include <math.h>
#include <stdint.h>

#define N_ 4096
#define T_ 4
#define F_ 256
#define H_ 8
#define C_ 16
#define P_ 1024
#define D_ 32
#define NT_ (N_*T_)
#define MAXTILES 67

#define BK 32
#define APAD 40
#define BPAD 40

// k2_mma: BM=128, BN=256, 512 threads, 4 stages, sync per 2 chunks
#define K2BM 128
#define K2NCH (N_/BK)
#define K2_A(s)     ((s) * 10240)                 // 4 stages
#define K2_B(s)     (40960 + (s)*20480)            // 4 stages
#define K2_RS       122880
#define K2_RQ       124928
#define K2_RINV     126976
#define SMEM_K2     127488

// k_proj_all / k_gemm3: M=64 tile, single-pass fp16
#define GA(s)        ((s) * 5120)
#define GB(s)        (10240 + (s)*20480)
#define GIDX         51200
#define GRED         51456
#define SMEM_G       52736
#define GKCH         (F_/BK)

// ---- scratch (static device globals) ----
__device__ float g_feat[N_*F_];
__device__ float g_recon[NT_*F_];
__device__ float g_edgefea[NT_*F_];
__device__ float g_nodeproj[N_*F_];
__device__ float g_edgeproj[NT_*F_];
__device__ float g_rowsum[NT_];
__device__ float g_rowsumsq[NT_];
__device__ float g_rownorm[NT_];
__device__ int   g_perm[N_];
__device__ int   g_tile_s[MAXTILES];
__device__ int   g_tile_start[MAXTILES];
__device__ int   g_tile_cnt[MAXTILES];
__device__ __align__(16) __half g_fT16[F_*N_];
__device__ __align__(16) __half g_W16[37*F_*F_];

// ---- helpers ----
__device__ __forceinline__ uint32_t smem_u32(const void* p) {
    uint32_t a;
    asm("{ .reg .u64 t; cvta.to.shared.u64 t, %1; cvt.u32.u64 %0, t; }"
        : "=r"(a) : "l"(p));
    return a;
}
__device__ __forceinline__ float4 ldg4(const float* p) {
    float4 v;
    asm volatile("ld.global.nc.v4.f32 {%0,%1,%2,%3}, [%4];"
                 : "=f"(v.x), "=f"(v.y), "=f"(v.z), "=f"(v.w) : "l"(p));
    return v;
}
__device__ __forceinline__ void ldm_x4(uint32_t* r, uint32_t addr) {
    asm volatile("ldmatrix.sync.aligned.m8n8.x4.shared.b16 {%0,%1,%2,%3}, [%4];"
                 : "=r"(r[0]), "=r"(r[1]), "=r"(r[2]), "=r"(r[3]) : "r"(addr));
}
__device__ __forceinline__ void mma_f16(float* d, const uint32_t* a,
                                        uint32_t b0, uint32_t b1) {
    asm volatile("mma.sync.aligned.m16n8k16.row.col.f32.f16.f16.f32 "
                 "{%0,%1,%2,%3}, {%4,%5,%6,%7}, {%8,%9}, {%0,%1,%2,%3};"
                 : "+f"(d[0]), "+f"(d[1]), "+f"(d[2]), "+f"(d[3])
                 : "r"(a[0]), "r"(a[1]), "r"(a[2]), "r"(a[3]), "r"(b0), "r"(b1));
}
__device__ __forceinline__ void cpa16(uint32_t dst, const void* src) {
    asm volatile("cp.async.cg.shared.global [%0], [%1], 16;" :: "r"(dst), "l"(src));
}
#define CP_COMMIT() asm volatile("cp.async.commit_group;" ::: "memory")
#define CP_WAIT0()  asm volatile("cp.async.wait_group 0;"  ::: "memory")

__device__ __forceinline__ void pack_ls_f16(float4 L0, float4 L1, float4 M0, float4 M1,
                                            float& psum, float& psq,
                                            uint32_t* Ah)
{
    float v[8];
    v[0] = fmaxf(L0.x * M0.x, 0.f); v[1] = fmaxf(L0.y * M0.y, 0.f);
    v[2] = fmaxf(L0.z * M0.z, 0.f); v[3] = fmaxf(L0.w * M0.w, 0.f);
    v[4] = fmaxf(L1.x * M1.x, 0.f); v[5] = fmaxf(L1.y * M1.y, 0.f);
    v[6] = fmaxf(L1.z * M1.z, 0.f); v[7] = fmaxf(L1.w * M1.w, 0.f);
    #pragma unroll
    for (int i = 0; i < 8; i++) { psum += v[i]; psq = fmaf(v[i], v[i], psq); }
    #pragma unroll
    for (int p = 0; p < 4; p++) {
        __half2 hp = __floats2half2_rn(v[2*p], v[2*p+1]);
        Ah[p] = *(uint32_t*)&hp;
    }
}

__device__ __forceinline__ void pack_f16(float4 a, float4 b, uint32_t* Ah)
{
    __half2 h0 = __floats2half2_rn(a.x, a.y);
    __half2 h1 = __floats2half2_rn(a.z, a.w);
    __half2 h2 = __floats2half2_rn(b.x, b.y);
    __half2 h3 = __floats2half2_rn(b.z, b.w);
    Ah[0] = *(uint32_t*)&h0;
    Ah[1] = *(uint32_t*)&h1;
    Ah[2] = *(uint32_t*)&h2;
    Ah[3] = *(uint32_t*)&h3;
}

// ============================================================
// K2-MMA: BM=128, BN=256, 512 threads, fp16 1-pass,
// 4 smem stages, ONE barrier per 2 chunks.
// ============================================================
__global__ __launch_bounds__(512, 1) void k2_mma(const float* __restrict__ linear,
                                                 const float* __restrict__ mask)
{
    extern __shared__ char sm[];
    const uint32_t sb = smem_u32(sm);
    const int tid = threadIdx.x;
    const int wid = tid >> 5, lane = tid & 31;
    const int warp_m = wid & 3, warp_n = wid >> 2;
    const int ntBase = blockIdx.x * K2BM;

    const int arow = tid >> 2;
    const int akof = (tid & 3) * 8;
    const float* lptr = linear + (size_t)(ntBase + arow) * N_ + akof;
    const float* mptr = mask   + (size_t)(ntBase + arow) * N_ + akof;
    const uint32_t aSt = (uint32_t)(arow * APAD + akof) * 2;

    const int brow = tid & 255;
    const int bhalf = tid >> 8;
    const char* bsrc = (const char*)(g_fT16 + (size_t)brow * N_) + bhalf * 32;
    const uint32_t bSt = (uint32_t)(brow * BPAD) * 2 + bhalf * 32;

    float psum = 0.f, psq = 0.f;
    uint32_t Ah[4];
    float4 La, Lb, Ma, Mb;

    const int aRowL = warp_m * 32 + (lane & 7) + ((lane >> 3) & 1) * 8;
    const int aColL = (lane >> 4) * 8;
    const int bRowL = warp_n * 64 + (lane & 7) + ((lane >> 4) & 1) * 8;
    const int bColL = ((lane >> 3) & 1) * 8;

    // ---- prologue: produce chunks 0 and 1 ----
    #pragma unroll
    for (int pc = 0; pc < 2; pc++) {
        const float* lp = lptr + pc * BK;
        const float* mp = mptr + pc * BK;
        La = ldg4(lp); Lb = ldg4(lp + 4);
        Ma = ldg4(mp); Mb = ldg4(mp + 4);
        uint32_t d = sb + K2_B(pc) + bSt;
        cpa16(d, bsrc + (size_t)pc * BK * 2);
        cpa16(d + 16, bsrc + (size_t)pc * BK * 2 + 16);
        pack_ls_f16(La, Lb, Ma, Mb, psum, psq, Ah);
        *(uint4*)(sm + K2_A(pc) + aSt) = make_uint4(Ah[0], Ah[1], Ah[2], Ah[3]);
    }
    CP_COMMIT();
    CP_WAIT0();
    __syncthreads();

    float acc[2][8][4];
    #pragma unroll
    for (int i = 0; i < 2; i++)
        #pragma unroll
        for (int j = 0; j < 8; j++)
            #pragma unroll
            for (int q = 0; q < 4; q++) acc[i][j][q] = 0.f;

    for (int c = 0; c < K2NCH; c += 2) {
        const bool more = (c + 2 < K2NCH);
        const int s0 = c & 3, s1 = (c + 1) & 3;
        const int p0 = (c + 2) & 3, p1 = (c + 3) & 3;

        if (more) {
            // issue B cp.async for both next chunks + A LDG for chunk c+2
            uint32_t d0 = sb + K2_B(p0) + bSt;
            uint32_t d1 = sb + K2_B(p1) + bSt;
            const char* s0p = bsrc + (size_t)(c + 2) * BK * 2;
            const char* s1p = bsrc + (size_t)(c + 3) * BK * 2;
            cpa16(d0, s0p);      cpa16(d0 + 16, s0p + 16);
            cpa16(d1, s1p);      cpa16(d1 + 16, s1p + 16);
            CP_COMMIT();
            const float* lp = lptr + (c + 2) * BK;
            const float* mp = mptr + (c + 2) * BK;
            La = ldg4(lp); Lb = ldg4(lp + 4);
            Ma = ldg4(mp); Mb = ldg4(mp + 4);
        }

        // ---- MMA chunk c ----
        {
            const uint32_t aB = sb + K2_A(s0);
            const uint32_t bB = sb + K2_B(s0);
            #pragma unroll
            for (int ks = 0; ks < BK; ks += 16) {
                uint32_t ah[2][4], bb[4][4];
                ldm_x4(ah[0], aB + (uint32_t)((aRowL)      * APAD + ks + aColL) * 2);
                ldm_x4(ah[1], aB + (uint32_t)((aRowL + 16) * APAD + ks + aColL) * 2);
                #pragma unroll
                for (int g = 0; g < 4; g++)
                    ldm_x4(bb[g], bB + (uint32_t)((bRowL + g * 16) * BPAD + ks + bColL) * 2);
                #pragma unroll
                for (int mf = 0; mf < 2; mf++)
                    #pragma unroll
                    for (int nf = 0; nf < 8; nf++)
                        mma_f16(acc[mf][nf], ah[mf],
                                bb[nf >> 1][(nf & 1) * 2], bb[nf >> 1][(nf & 1) * 2 + 1]);
            }
        }

        if (more) {
            // pack + STS chunk c+2 ; LDG chunk c+3
            pack_ls_f16(La, Lb, Ma, Mb, psum, psq, Ah);
            *(uint4*)(sm + K2_A(p0) + aSt) = make_uint4(Ah[0], Ah[1], Ah[2], Ah[3]);
            const float* lp = lptr + (c + 3) * BK;
            const float* mp = mptr + (c + 3) * BK;
            La = ldg4(lp); Lb = ldg4(lp + 4);
            Ma = ldg4(mp); Mb = ldg4(mp + 4);
        }

        // ---- MMA chunk c+1 ----
        {
            const uint32_t aB = sb + K2_A(s1);
            const uint32_t bB = sb + K2_B(s1);
            #pragma unroll
            for (int ks = 0; ks < BK; ks += 16) {
                uint32_t ah[2][4], bb[4][4];
                ldm_x4(ah[0], aB + (uint32_t)((aRowL)      * APAD + ks + aColL) * 2);
                ldm_x4(ah[1], aB + (uint32_t)((aRowL + 16) * APAD + ks + aColL) * 2);
                #pragma unroll
                for (int g = 0; g < 4; g++)
                    ldm_x4(bb[g], bB + (uint32_t)((bRowL + g * 16) * BPAD + ks + bColL) * 2);
                #pragma unroll
                for (int mf = 0; mf < 2; mf++)
                    #pragma unroll
                    for (int nf = 0; nf < 8; nf++)
                        mma_f16(acc[mf][nf], ah[mf],
                                bb[nf >> 1][(nf & 1) * 2], bb[nf >> 1][(nf & 1) * 2 + 1]);
            }
        }

        if (more) {
            pack_ls_f16(La, Lb, Ma, Mb, psum, psq, Ah);
            *(uint4*)(sm + K2_A(p1) + aSt) = make_uint4(Ah[0], Ah[1], Ah[2], Ah[3]);
            CP_WAIT0();
            __syncthreads();       // ONE barrier per 2 chunks
        }
    }

    ((float*)(sm + K2_RS))[arow * 4 + (tid & 3)] = psum;
    ((float*)(sm + K2_RQ))[arow * 4 + (tid & 3)] = psq;
    __syncthreads();
    if (tid < K2BM) {
        const float* rs = (const float*)(sm + K2_RS) + tid * 4;
        const float* rq = (const float*)(sm + K2_RQ) + tid * 4;
        float ss = (rs[0] + rs[1]) + (rs[2] + rs[3]);
        float sq = (rq[0] + rq[1]) + (rq[2] + rq[3]);
        g_rowsum[ntBase + tid]   = ss;
        g_rowsumsq[ntBase + tid] = sq;
        ((float*)(sm + K2_RINV))[tid] = 1.f / (ss + 1.f);
    }
    __syncthreads();
    const float* rinv = (const float*)(sm + K2_RINV);

    #pragma unroll
    for (int mf = 0; mf < 2; mf++) {
        #pragma unroll
        for (int half = 0; half < 2; half++) {
            int row = warp_m * 32 + mf * 16 + half * 8 + (lane >> 2);
            int nt = ntBase + row;
            float inv = rinv[row];
            const float* fb = g_feat + (size_t)(nt >> 2) * F_;
            float* rb = g_recon   + (size_t)nt * F_;
            float* eb = g_edgefea + (size_t)nt * F_;
            #pragma unroll
            for (int nf = 0; nf < 8; nf++) {
                int col = warp_n * 64 + nf * 8 + (lane & 3) * 2;
                float d0 = acc[mf][nf][half * 2];
                float d1 = acc[mf][nf][half * 2 + 1];
                *(float2*)(rb + col) = make_float2(d0, d1);
                float2 fv = *(const float2*)(fb + col);
                *(float2*)(eb + col) = make_float2((d0 + fv.x) * inv, (d1 + fv.y) * inv);
            }
        }
    }
}

// ============================================================
// K_proj_all: merged bucketed projections, single-pass fp16.
// ============================================================
__global__ __launch_bounds__(256, 2) void k_proj_all()
{
    extern __shared__ char sm[];
    const uint32_t sb = smem_u32(sm);
    const int tid = threadIdx.x;
    const int wid = tid >> 5, lane = tid & 31;
    const int warp_m = wid & 1, warp_n = wid >> 1;

    const int t = blockIdx.x;
    const int cnt = g_tile_cnt[t];
    if (cnt == 0) return;
    const int s = g_tile_s[t];
    const int y = blockIdx.y;
    int mode, j = 0;
    if (y < 4)       { mode = 0; j = y; }
    else if (y == 4) { mode = 1; }
    else             { mode = 2; j = y - 5; }

    int* sidx = (int*)(sm + GIDX);
    const int start = g_tile_start[t];
    if (tid < 64) sidx[tid] = g_perm[start + min(tid, cnt - 1)];
    __syncthreads();

    const int arow = tid >> 2;
    const int akof = (tid & 3) * 8;
    const float* aptr;
    if (mode == 2) aptr = g_edgefea + ((size_t)sidx[arow] * T_ + j) * F_ + akof;
    else           aptr = g_feat + (size_t)sidx[arow] * F_ + akof;
    const uint32_t aSt = (uint32_t)(arow * APAD + akof) * 2;

    int z;
    if (mode == 0)      z = 1 + s * T_ + j;
    else if (mode == 1) z = 17 + s;
    else                z = 21 + s * T_ + j;
    const char* b_src = (const char*)(g_W16 + (size_t)z * F_ * F_ + (size_t)tid * F_);
    const uint32_t bSt = (uint32_t)(tid * BPAD) * 2;

    const int aRowL = warp_m * 32 + (lane & 7) + ((lane >> 3) & 1) * 8;
    const int aColL = (lane >> 4) * 8;
    const int bRowL = warp_n * 64 + (lane & 7) + ((lane >> 4) & 1) * 8;
    const int bColL = ((lane >> 3) & 1) * 8;

    uint32_t Ah[4];
    float4 Aa, Ab;

    Aa = ldg4(aptr); Ab = ldg4(aptr + 4);
    {
        uint32_t d = sb + GB(0) + bSt;
        #pragma unroll
        for (int q = 0; q < 4; q++) cpa16(d + q * 16, b_src + q * 16);
    }
    CP_COMMIT();
    pack_f16(Aa, Ab, Ah);
    *(uint4*)(sm + GA(0) + aSt) = make_uint4(Ah[0], Ah[1], Ah[2], Ah[3]);
    CP_WAIT0();
    __syncthreads();

    float acc[2][8][4];
    #pragma unroll
    for (int i = 0; i < 2; i++)
        #pragma unroll
        for (int q = 0; q < 8; q++)
            #pragma unroll
            for (int e = 0; e < 4; e++) acc[i][q][e] = 0.f;

    for (int c = 0; c < GKCH; c++) {
        const int st = c & 1;
        const bool more = (c + 1 < GKCH);
        if (more) {
            uint32_t d = sb + GB(st ^ 1) + bSt;
            const char* srcb = b_src + (size_t)(c + 1) * BK * 2;
            #pragma unroll
            for (int q = 0; q < 4; q++) cpa16(d + q * 16, srcb + q * 16);
            CP_COMMIT();
            Aa = ldg4(aptr + (c + 1) * BK);
            Ab = ldg4(aptr + (c + 1) * BK + 4);
        }

        const uint32_t aB = sb + GA(st);
        const uint32_t bB = sb + GB(st);

        #pragma unroll
        for (int ks = 0; ks < BK; ks += 16) {
            uint32_t ah[2][4], bb[4][4];
            ldm_x4(ah[0], aB + (uint32_t)((aRowL)      * APAD + ks + aColL) * 2);
            ldm_x4(ah[1], aB + (uint32_t)((aRowL + 16) * APAD + ks + aColL) * 2);
            #pragma unroll
            for (int g = 0; g < 4; g++)
                ldm_x4(bb[g], bB + (uint32_t)((bRowL + g * 16) * BPAD + ks + bColL) * 2);
            #pragma unroll
            for (int mf = 0; mf < 2; mf++)
                #pragma unroll
                for (int nf = 0; nf < 8; nf++)
                    mma_f16(acc[mf][nf], ah[mf],
                            bb[nf >> 1][(nf & 1) * 2], bb[nf >> 1][(nf & 1) * 2 + 1]);
        }

        if (more) {
            pack_f16(Aa, Ab, Ah);
            *(uint4*)(sm + GA(st^1) + aSt) = make_uint4(Ah[0], Ah[1], Ah[2], Ah[3]);
            CP_WAIT0();
            __syncthreads();
        }
    }

    if (mode == 0) {
        float* sred = (float*)(sm + GRED);
        #pragma unroll
        for (int mf = 0; mf < 2; mf++) {
            #pragma unroll
            for (int half = 0; half < 2; half++) {
                int row = warp_m * 32 + mf * 16 + half * 8 + (lane >> 2);
                int node = sidx[row];
                const float* rr = g_recon + ((size_t)node * T_ + j) * F_;
                float part = 0.f;
                #pragma unroll
                for (int nf = 0; nf < 8; nf++) {
                    int col = warp_n * 64 + nf * 8 + (lane & 3) * 2;
                    float2 rv = *(const float2*)(rr + col);
                    float d0 = acc[mf][nf][half * 2]     - rv.x;
                    float d1 = acc[mf][nf][half * 2 + 1] - rv.y;
                    part = fmaf(d0, d0, part);
                    part = fmaf(d1, d1, part);
                }
                part += __shfl_xor_sync(0xffffffffu, part, 1);
                part += __shfl_xor_sync(0xffffffffu, part, 2);
                if ((lane & 3) == 0) sred[row * 4 + warp_n] = part;
            }
        }
        __syncthreads();
        if (tid < 64) {
            const float* r4 = sred + tid * 4;
            float tot = (r4[0] + r4[1]) + (r4[2] + r4[3]);
            if (tid < cnt)
                g_rownorm[sidx[tid] * T_ + j] = sqrtf(tot);
        }
    } else {
        #pragma unroll
        for (int mf = 0; mf < 2; mf++) {
            #pragma unroll
            for (int half = 0; half < 2; half++) {
                int row = warp_m * 32 + mf * 16 + half * 8 + (lane >> 2);
                if (row >= cnt) continue;
                int node = sidx[row];
                float* ob;
                if (mode == 1) ob = g_nodeproj + (size_t)node * F_;
                else           ob = g_edgeproj + ((size_t)node * T_ + j) * F_;
                #pragma unroll
                for (int nf = 0; nf < 8; nf++) {
                    int col = warp_n * 64 + nf * 8 + (lane & 3) * 2;
                    *(float2*)(ob + col) = make_float2(acc[mf][nf][half * 2],
                                                       acc[mf][nf][half * 2 + 1]);
                }
            }
        }
    }
}

// ============================================================
// K_gemm3: g_feat = feature @ theta^T + bias (single-pass fp16)
// ============================================================
__global__ __launch_bounds__(256, 2) void k_gemm3(const float* __restrict__ Ain,
                                                  const float* __restrict__ bias)
{
    extern __shared__ char sm[];
    const uint32_t sb = smem_u32(sm);
    const int tid = threadIdx.x;
    const int wid = tid >> 5, lane = tid & 31;
    const int warp_m = wid & 1, warp_n = wid >> 1;
    const int mBase = blockIdx.x * 64;

    const int arow = tid >> 2;
    const int akof = (tid & 3) * 8;
    const float* aptr = Ain + (size_t)(mBase + arow) * F_ + akof;
    const uint32_t aSt = (uint32_t)(arow * APAD + akof) * 2;

    const char* b_src = (const char*)(g_W16 + (size_t)tid * F_);
    const uint32_t bSt = (uint32_t)(tid * BPAD) * 2;

    const int aRowL = warp_m * 32 + (lane & 7) + ((lane >> 3) & 1) * 8;
    const int aColL = (lane >> 4) * 8;
    const int bRowL = warp_n * 64 + (lane & 7) + ((lane >> 4) & 1) * 8;
    const int bColL = ((lane >> 3) & 1) * 8;

    uint32_t Ah[4];
    float4 Aa, Ab;

    Aa = ldg4(aptr); Ab = ldg4(aptr + 4);
    {
        uint32_t d = sb + GB(0) + bSt;
        #pragma unroll
        for (int q = 0; q < 4; q++) cpa16(d + q * 16, b_src + q * 16);
    }
    CP_COMMIT();
    pack_f16(Aa, Ab, Ah);
    *(uint4*)(sm + GA(0) + aSt) = make_uint4(Ah[0], Ah[1], Ah[2], Ah[3]);
    CP_WAIT0();
    __syncthreads();

    float acc[2][8][4];
    #pragma unroll
    for (int i = 0; i < 2; i++)
        #pragma unroll
        for (int q = 0; q < 8; q++)
            #pragma unroll
            for (int e = 0; e < 4; e++) acc[i][q][e] = 0.f;

    for (int c = 0; c < GKCH; c++) {
        const int st = c & 1;
        const bool more = (c + 1 < GKCH);
        if (more) {
            uint32_t d = sb + GB(st ^ 1) + bSt;
            const char* srcb = b_src + (size_t)(c + 1) * BK * 2;
            #pragma unroll
            for (int q = 0; q < 4; q++) cpa16(d + q * 16, srcb + q * 16);
            CP_COMMIT();
            Aa = ldg4(aptr + (c + 1) * BK);
            Ab = ldg4(aptr + (c + 1) * BK + 4);
        }

        const uint32_t aB = sb + GA(st);
        const uint32_t bB = sb + GB(st);

        #pragma unroll
        for (int ks = 0; ks < BK; ks += 16) {
            uint32_t ah[2][4], bb[4][4];
            ldm_x4(ah[0], aB + (uint32_t)((aRowL)      * APAD + ks + aColL) * 2);
            ldm_x4(ah[1], aB + (uint32_t)((aRowL + 16) * APAD + ks + aColL) * 2);
            #pragma unroll
            for (int g = 0; g < 4; g++)
                ldm_x4(bb[g], bB + (uint32_t)((bRowL + g * 16) * BPAD + ks + bColL) * 2);
            #pragma unroll
            for (int mf = 0; mf < 2; mf++)
                #pragma unroll
                for (int nf = 0; nf < 8; nf++)
                    mma_f16(acc[mf][nf], ah[mf],
                            bb[nf >> 1][(nf & 1) * 2], bb[nf >> 1][(nf & 1) * 2 + 1]);
        }

        if (more) {
            pack_f16(Aa, Ab, Ah);
            *(uint4*)(sm + GA(st^1) + aSt) = make_uint4(Ah[0], Ah[1], Ah[2], Ah[3]);
            CP_WAIT0();
            __syncthreads();
        }
    }

    #pragma unroll
    for (int mf = 0; mf < 2; mf++) {
        #pragma unroll
        for (int half = 0; half < 2; half++) {
            int row = warp_m * 32 + mf * 16 + half * 8 + (lane >> 2);
            float* ob = g_feat + (size_t)(mBase + row) * F_;
            #pragma unroll
            for (int nf = 0; nf < 8; nf++) {
                int col = warp_n * 64 + nf * 8 + (lane & 3) * 2;
                *(float2*)(ob + col) = make_float2(acc[mf][nf][half * 2] + bias[col],
                                                   acc[mf][nf][half * 2 + 1] + bias[col + 1]);
            }
        }
    }
}

// ============================================================
// K_wconv: weights fp32 -> fp16
// ============================================================
__global__ __launch_bounds__(256) void k_wconv(const float* __restrict__ th,
                                               const float* __restrict__ rp,
                                               const float* __restrict__ np,
                                               const float* __restrict__ ep)
{
    int i4 = blockIdx.x * 256 + threadIdx.x;
    int i = i4 * 4;
    int z = i >> 16;
    int off = i & 65535;
    const float* src;
    if (z == 0)      src = th;
    else if (z < 17) src = rp + (size_t)(z - 1)  * 65536;
    else if (z < 21) src = np + (size_t)(z - 17) * 65536;
    else             src = ep + (size_t)(z - 21) * 65536;
    float4 v = ldg4(src + off);
    __half2 h0 = __floats2half2_rn(v.x, v.y);
    __half2 h1 = __floats2half2_rn(v.z, v.w);
    *(uint2*)(g_W16 + i) = make_uint2(*(uint32_t*)&h0, *(uint32_t*)&h1);
}

// ============================================================
// K_featT: featT fp16 [F_][N_] from g_feat
// ============================================================
__global__ void k_featT()
{
    __shared__ float tile[32][33];
    int x = blockIdx.x * 32 + threadIdx.x;
    int y = blockIdx.y * 32 + threadIdx.y;
    #pragma unroll
    for (int i = 0; i < 32; i += 8)
        tile[threadIdx.y + i][threadIdx.x] = g_feat[(size_t)(y + i) * F_ + x];
    __syncthreads();
    int f2 = blockIdx.x * 32 + threadIdx.y;
    int n2 = blockIdx.y * 32 + threadIdx.x;
    #pragma unroll
    for (int i = 0; i < 32; i += 8) {
        float v = tile[threadIdx.x][threadIdx.y + i];
        g_fT16[(size_t)(f2 + i) * N_ + n2] = __float2half_rn(v);
    }
}

// ============================================================
// K_sort
// ============================================================
__global__ __launch_bounds__(256) void k_sort(const int* __restrict__ nmm)
{
    __shared__ int hist[4][256];
    __shared__ int basep[4][256];
    __shared__ int btot[4];
    __shared__ int boff[4];

    const int tid = threadIdx.x;
    const int r0 = tid * 16;
    int myb[16];
    int c[4] = {0, 0, 0, 0};
    #pragma unroll
    for (int i = 0; i < 16; i++) {
        int b = nmm[r0 + i];
        myb[i] = b;
        c[b]++;
    }
    #pragma unroll
    for (int b = 0; b < 4; b++) hist[b][tid] = c[b];
    __syncthreads();

    const int w = tid >> 5, lane = tid & 31;
    if (w < 4) {
        int b = w;
        int loc[8];
        int sum = 0;
        #pragma unroll
        for (int q = 0; q < 8; q++) {
            loc[q] = sum;
            sum += hist[b][lane * 8 + q];
        }
        int pre = sum;
        #pragma unroll
        for (int off = 1; off < 32; off <<= 1) {
            int v = __shfl_up_sync(0xffffffffu, pre, off);
            if (lane >= off) pre += v;
        }
        int tot = __shfl_sync(0xffffffffu, pre, 31);
        pre -= sum;
        #pragma unroll
        for (int q = 0; q < 8; q++) basep[b][lane * 8 + q] = pre + loc[q];
        if (lane == 31) btot[b] = tot;
    }
    __syncthreads();

    if (tid == 0) {
        int off = 0, t = 0;
        for (int b = 0; b < 4; b++) {
            boff[b] = off;
            int cnt = btot[b];
            for (int k = 0; k < cnt; k += 64) {
                g_tile_s[t] = b;
                g_tile_start[t] = off + k;
                g_tile_cnt[t] = min(64, cnt - k);
                t++;
            }
            off += cnt;
        }
        for (; t < MAXTILES; t++) { g_tile_cnt[t] = 0; g_tile_s[t] = 0; g_tile_start[t] = 0; }
    }
    __syncthreads();

    int pos[4];
    #pragma unroll
    for (int b = 0; b < 4; b++) pos[b] = boff[b] + basep[b][tid];
    #pragma unroll
    for (int i = 0; i < 16; i++) {
        int b = myb[i];
        g_perm[pos[b]++] = r0 + i;
    }
}

// ============================================================
// K_attn
// ============================================================
__global__ __launch_bounds__(256) void k_attn(float* __restrict__ node_rep)
{
    const int i = blockIdx.x, tid = threadIdx.x;
    const int h = tid >> 5, lane = tid & 31;
    __shared__ float sw[T_][H_];

    float np = g_nodeproj[(size_t)i * F_ + tid];
    const float inv = rsqrtf((float)D_);

    #pragma unroll
    for (int t = 0; t < T_; t++) {
        float v = np * g_edgeproj[((size_t)i * T_ + t) * F_ + tid];
        #pragma unroll
        for (int off = 16; off > 0; off >>= 1)
            v += __shfl_down_sync(0xffffffffu, v, off);
        if (lane == 0) sw[t][h] = v * inv;
    }
    __syncthreads();

    if (tid < T_) {
        int t = tid;
        float mx = sw[t][0];
        #pragma unroll
        for (int hh = 1; hh < H_; hh++) mx = fmaxf(mx, sw[t][hh]);
        float sm = 0.f;
        #pragma unroll
        for (int hh = 0; hh < H_; hh++) {
            float e = expf(sw[t][hh] - mx);
            sw[t][hh] = e;
            sm += e;
        }
        float r = 1.f / sm;
        #pragma unroll
        for (int hh = 0; hh < H_; hh++) sw[t][hh] *= r;
    }
    __syncthreads();

    float rep = 0.f;
    #pragma unroll
    for (int t = 0; t < T_; t++)
        rep += fmaxf(sw[t][h] * g_edgefea[((size_t)i * T_ + t) * F_ + tid], 0.f);
    node_rep[(size_t)i * F_ + tid] = rep;
}

// ============================================================
// K_pred
// ============================================================
__global__ __launch_bounds__(256) void k_pred(const float* __restrict__ node_rep,
                                              const int* __restrict__ node_idx,
                                              const float* __restrict__ pw,
                                              const float* __restrict__ pb,
                                              float* __restrict__ predict)
{
    const int warp = threadIdx.x >> 5, lane = threadIdx.x & 31;
    const int p = blockIdx.x * 8 + warp;
    const float* a = node_rep + (size_t)node_idx[p] * F_;

    float part[C_];
    #pragma unroll
    for (int c = 0; c < C_; c++) part[c] = 0.f;
    for (int f = lane; f < F_; f += 32) {
        float av = a[f];
        #pragma unroll
        for (int c = 0; c < C_; c++)
            part[c] = fmaf(av, pw[c * F_ + f], part[c]);
    }
    #pragma unroll
    for (int c = 0; c < C_; c++)
        #pragma unroll
        for (int off = 16; off > 0; off >>= 1)
            part[c] += __shfl_down_sync(0xffffffffu, part[c], off);

    if (lane == 0) {
        float sig[C_];
        float mx = -1e30f;
        #pragma unroll
        for (int c = 0; c < C_; c++) {
            float l = part[c] + pb[c];
            float sg = 1.f / (1.f + expf(-l));
            sig[c] = sg;
            mx = fmaxf(mx, sg);
        }
        float sm = 0.f;
        #pragma unroll
        for (int c = 0; c < C_; c++) {
            float e = expf(sig[c] - mx);
            sig[c] = e;
            sm += e;
        }
        float r = 1.f / sm;
        #pragma unroll
        for (int c = 0; c < C_; c++)
            predict[(size_t)p * C_ + c] = sig[c] * r;
    }
}

// ============================================================
// K_reduce
// ============================================================
__global__ __launch_bounds__(256) void k_reduce(float* __restrict__ lossOut)
{
    __shared__ float s1[256], s2[256], s3[256];
    int tid = threadIdx.x;
    float l1 = 0.f, l2 = 0.f, re = 0.f;
    for (int i = tid; i < NT_; i += 256) {
        l1 += g_rowsum[i];
        l2 += sqrtf(g_rowsumsq[i]);
        re += g_rownorm[i];
    }
    s1[tid] = l1; s2[tid] = l2; s3[tid] = re;
    __syncthreads();
    for (int off = 128; off > 0; off >>= 1) {
        if (tid < off) {
            s1[tid] += s1[tid + off];
            s2[tid] += s2[tid + off];
            s3[tid] += s3[tid + off];
        }
        __syncthreads();
    }
    if (tid == 0)
        lossOut[0] = 0.1f * (0.01f * s3[0] + 0.2f * s2[0] + s1[0]);
}

// ============================================================
extern "C" void kernel_launch(void* const* d_in, const int* in_sizes, int n_in,
                              void* d_out, int out_size)
{
    (void)in_sizes; (void)n_in; (void)out_size;
    const float* feature  = (const float*)d_in[0];
    const float* mask     = (const float*)d_in[1];
    const int*   nmm      = (const int*)  d_in[2];
    const int*   node_idx = (const int*)  d_in[3];
    const float* theta_w  = (const float*)d_in[4];
    const float* theta_b  = (const float*)d_in[5];
    const float* linear   = (const float*)d_in[6];
    const float* rp       = (const float*)d_in[7];
    const float* mhnp     = (const float*)d_in[8];
    const float* mhep     = (const float*)d_in[9];
    const float* pw       = (const float*)d_in[10];
    const float* pb       = (const float*)d_in[11];

    float* out      = (float*)d_out;
    float* predict  = out;
    float* loss     = out + P_ * C_;
    float* node_rep = out + P_ * C_ + 1;

    cudaFuncSetAttribute(k2_mma,     cudaFuncAttributeMaxDynamicSharedMemorySize, SMEM_K2);
    cudaFuncSetAttribute(k_proj_all, cudaFuncAttributeMaxDynamicSharedMemorySize, SMEM_G);
    cudaFuncSetAttribute(k_gemm3,    cudaFuncAttributeMaxDynamicSharedMemorySize, SMEM_G);

    // k2 placed 4th => lands in the profiled slot
    k_wconv<<<37 * 65536 / 1024, 256>>>(theta_w, rp, mhnp, mhep);
    k_gemm3<<<N_ / 64, 256, SMEM_G>>>(feature, theta_b);
    k_featT<<<dim3(8, 128), dim3(32, 8)>>>();
    k2_mma<<<NT_ / K2BM, 512, SMEM_K2>>>(linear, mask);
    k_sort<<<1, 256>>>(nmm);
    k_proj_all<<<dim3(MAXTILES, 9), 256, SMEM_G>>>();
    k_attn<<<N_, 256>>>(node_rep);
    k_pred<<<P_ / 8, 256>>>(node_rep, node_idx, pw, pb, predict);
    k_reduce<<<1, 256>>>(loss);
}

// round 17
// speedup vs baseline: 1.2361x; 1.0643x over previous
#include <cuda_runtime.h>
#include <cuda_fp16.h>
#include <math.h>
#include <stdint.h>

#define N_ 4096
#define T_ 4
#define F_ 256
#define H_ 8
#define C_ 16
#define P_ 1024
#define D_ 32
#define NT_ (N_*T_)
#define MAXTILES 67

#define BK 32
#define APAD 40
#define BPAD 40

// k2_mma: BM=128, BN=256, 512 threads, 4 stages, sync per 2 chunks
#define K2BM 128
#define K2NCH (N_/BK)
#define K2_A(s)     ((s) * 10240)
#define K2_B(s)     (40960 + (s)*20480)
#define K2_RS       122880
#define K2_RQ       124928
#define K2_RINV     126976
#define SMEM_K2     127488

// k_proj_all / k_gemm3: M=64 tile, single-pass fp16
#define GA(s)        ((s) * 5120)
#define GB(s)        (10240 + (s)*20480)
#define GIDX         51200
#define GRED         51456
#define SMEM_G       52736
#define GKCH         (F_/BK)

// ---- scratch (static device globals) ----
__device__ float g_feat[N_*F_];
__device__ float g_recon[NT_*F_];
__device__ float g_edgefea[NT_*F_];
__device__ float g_nodeproj[N_*F_];
__device__ float g_edgeproj[NT_*F_];
__device__ float g_rowsum[NT_];
__device__ float g_rowsumsq[NT_];
__device__ float g_rownorm[NT_];
__device__ int   g_perm[N_];
__device__ int   g_tile_s[MAXTILES];
__device__ int   g_tile_start[MAXTILES];
__device__ int   g_tile_cnt[MAXTILES];
__device__ __align__(16) __half g_fT16[F_*N_];
__device__ __align__(16) __half g_W16[37*F_*F_];

// ---- helpers ----
__device__ __forceinline__ uint32_t smem_u32(const void* p) {
    uint32_t a;
    asm("{ .reg .u64 t; cvta.to.shared.u64 t, %1; cvt.u32.u64 %0, t; }"
        : "=r"(a) : "l"(p));
    return a;
}
__device__ __forceinline__ float4 ldg4(const float* p) {
    float4 v;
    asm volatile("ld.global.nc.v4.f32 {%0,%1,%2,%3}, [%4];"
                 : "=f"(v.x), "=f"(v.y), "=f"(v.z), "=f"(v.w) : "l"(p));
    return v;
}
__device__ __forceinline__ void ldm_x4(uint32_t* r, uint32_t addr) {
    asm volatile("ldmatrix.sync.aligned.m8n8.x4.shared.b16 {%0,%1,%2,%3}, [%4];"
                 : "=r"(r[0]), "=r"(r[1]), "=r"(r[2]), "=r"(r[3]) : "r"(addr));
}
__device__ __forceinline__ void mma_f16(float* d, const uint32_t* a,
                                        uint32_t b0, uint32_t b1) {
    asm volatile("mma.sync.aligned.m16n8k16.row.col.f32.f16.f16.f32 "
                 "{%0,%1,%2,%3}, {%4,%5,%6,%7}, {%8,%9}, {%0,%1,%2,%3};"
                 : "+f"(d[0]), "+f"(d[1]), "+f"(d[2]), "+f"(d[3])
                 : "r"(a[0]), "r"(a[1]), "r"(a[2]), "r"(a[3]), "r"(b0), "r"(b1));
}
__device__ __forceinline__ void cpa16(uint32_t dst, const void* src) {
    asm volatile("cp.async.cg.shared.global [%0], [%1], 16;" :: "r"(dst), "l"(src));
}
#define CP_COMMIT() asm volatile("cp.async.commit_group;" ::: "memory")
#define CP_WAIT0()  asm volatile("cp.async.wait_group 0;"  ::: "memory")

__device__ __forceinline__ void pack_ls_f16(float4 L0, float4 L1, float4 M0, float4 M1,
                                            float& psum, float& psq,
                                            uint32_t* Ah)
{
    float v[8];
    v[0] = fmaxf(L0.x * M0.x, 0.f); v[1] = fmaxf(L0.y * M0.y, 0.f);
    v[2] = fmaxf(L0.z * M0.z, 0.f); v[3] = fmaxf(L0.w * M0.w, 0.f);
    v[4] = fmaxf(L1.x * M1.x, 0.f); v[5] = fmaxf(L1.y * M1.y, 0.f);
    v[6] = fmaxf(L1.z * M1.z, 0.f); v[7] = fmaxf(L1.w * M1.w, 0.f);
    #pragma unroll
    for (int i = 0; i < 8; i++) { psum += v[i]; psq = fmaf(v[i], v[i], psq); }
    #pragma unroll
    for (int p = 0; p < 4; p++) {
        __half2 hp = __floats2half2_rn(v[2*p], v[2*p+1]);
        Ah[p] = *(uint32_t*)&hp;
    }
}

__device__ __forceinline__ void pack_f16(float4 a, float4 b, uint32_t* Ah)
{
    __half2 h0 = __floats2half2_rn(a.x, a.y);
    __half2 h1 = __floats2half2_rn(a.z, a.w);
    __half2 h2 = __floats2half2_rn(b.x, b.y);
    __half2 h3 = __floats2half2_rn(b.z, b.w);
    Ah[0] = *(uint32_t*)&h0;
    Ah[1] = *(uint32_t*)&h1;
    Ah[2] = *(uint32_t*)&h2;
    Ah[3] = *(uint32_t*)&h3;
}

// ============================================================
// K2-MMA: BM=128, BN=256, 512 threads, fp16 1-pass,
// 4 smem stages, ONE barrier per 2 chunks (champion config).
// ============================================================
__global__ __launch_bounds__(512, 1) void k2_mma(const float* __restrict__ linear,
                                                 const float* __restrict__ mask)
{
    extern __shared__ char sm[];
    const uint32_t sb = smem_u32(sm);
    const int tid = threadIdx.x;
    const int wid = tid >> 5, lane = tid & 31;
    const int warp_m = wid & 3, warp_n = wid >> 2;
    const int ntBase = blockIdx.x * K2BM;

    const int arow = tid >> 2;
    const int akof = (tid & 3) * 8;
    const float* lptr = linear + (size_t)(ntBase + arow) * N_ + akof;
    const float* mptr = mask   + (size_t)(ntBase + arow) * N_ + akof;
    const uint32_t aSt = (uint32_t)(arow * APAD + akof) * 2;

    const int brow = tid & 255;
    const int bhalf = tid >> 8;
    const char* bsrc = (const char*)(g_fT16 + (size_t)brow * N_) + bhalf * 32;
    const uint32_t bSt = (uint32_t)(brow * BPAD) * 2 + bhalf * 32;

    float psum = 0.f, psq = 0.f;
    uint32_t Ah[4];
    float4 La, Lb, Ma, Mb;

    const int aRowL = warp_m * 32 + (lane & 7) + ((lane >> 3) & 1) * 8;
    const int aColL = (lane >> 4) * 8;
    const int bRowL = warp_n * 64 + (lane & 7) + ((lane >> 4) & 1) * 8;
    const int bColL = ((lane >> 3) & 1) * 8;

    #pragma unroll
    for (int pc = 0; pc < 2; pc++) {
        const float* lp = lptr + pc * BK;
        const float* mp = mptr + pc * BK;
        La = ldg4(lp); Lb = ldg4(lp + 4);
        Ma = ldg4(mp); Mb = ldg4(mp + 4);
        uint32_t d = sb + K2_B(pc) + bSt;
        cpa16(d, bsrc + (size_t)pc * BK * 2);
        cpa16(d + 16, bsrc + (size_t)pc * BK * 2 + 16);
        pack_ls_f16(La, Lb, Ma, Mb, psum, psq, Ah);
        *(uint4*)(sm + K2_A(pc) + aSt) = make_uint4(Ah[0], Ah[1], Ah[2], Ah[3]);
    }
    CP_COMMIT();
    CP_WAIT0();
    __syncthreads();

    float acc[2][8][4];
    #pragma unroll
    for (int i = 0; i < 2; i++)
        #pragma unroll
        for (int j = 0; j < 8; j++)
            #pragma unroll
            for (int q = 0; q < 4; q++) acc[i][j][q] = 0.f;

    for (int c = 0; c < K2NCH; c += 2) {
        const bool more = (c + 2 < K2NCH);
        const int s0 = c & 3, s1 = (c + 1) & 3;
        const int p0 = (c + 2) & 3, p1 = (c + 3) & 3;

        if (more) {
            uint32_t d0 = sb + K2_B(p0) + bSt;
            uint32_t d1 = sb + K2_B(p1) + bSt;
            const char* s0p = bsrc + (size_t)(c + 2) * BK * 2;
            const char* s1p = bsrc + (size_t)(c + 3) * BK * 2;
            cpa16(d0, s0p);      cpa16(d0 + 16, s0p + 16);
            cpa16(d1, s1p);      cpa16(d1 + 16, s1p + 16);
            CP_COMMIT();
            const float* lp = lptr + (c + 2) * BK;
            const float* mp = mptr + (c + 2) * BK;
            La = ldg4(lp); Lb = ldg4(lp + 4);
            Ma = ldg4(mp); Mb = ldg4(mp + 4);
        }

        {
            const uint32_t aB = sb + K2_A(s0);
            const uint32_t bB = sb + K2_B(s0);
            #pragma unroll
            for (int ks = 0; ks < BK; ks += 16) {
                uint32_t ah[2][4], bb[4][4];
                ldm_x4(ah[0], aB + (uint32_t)((aRowL)      * APAD + ks + aColL) * 2);
                ldm_x4(ah[1], aB + (uint32_t)((aRowL + 16) * APAD + ks + aColL) * 2);
                #pragma unroll
                for (int g = 0; g < 4; g++)
                    ldm_x4(bb[g], bB + (uint32_t)((bRowL + g * 16) * BPAD + ks + bColL) * 2);
                #pragma unroll
                for (int mf = 0; mf < 2; mf++)
                    #pragma unroll
                    for (int nf = 0; nf < 8; nf++)
                        mma_f16(acc[mf][nf], ah[mf],
                                bb[nf >> 1][(nf & 1) * 2], bb[nf >> 1][(nf & 1) * 2 + 1]);
            }
        }

        if (more) {
            pack_ls_f16(La, Lb, Ma, Mb, psum, psq, Ah);
            *(uint4*)(sm + K2_A(p0) + aSt) = make_uint4(Ah[0], Ah[1], Ah[2], Ah[3]);
            const float* lp = lptr + (c + 3) * BK;
            const float* mp = mptr + (c + 3) * BK;
            La = ldg4(lp); Lb = ldg4(lp + 4);
            Ma = ldg4(mp); Mb = ldg4(mp + 4);
        }

        {
            const uint32_t aB = sb + K2_A(s1);
            const uint32_t bB = sb + K2_B(s1);
            #pragma unroll
            for (int ks = 0; ks < BK; ks += 16) {
                uint32_t ah[2][4], bb[4][4];
                ldm_x4(ah[0], aB + (uint32_t)((aRowL)      * APAD + ks + aColL) * 2);
                ldm_x4(ah[1], aB + (uint32_t)((aRowL + 16) * APAD + ks + aColL) * 2);
                #pragma unroll
                for (int g = 0; g < 4; g++)
                    ldm_x4(bb[g], bB + (uint32_t)((bRowL + g * 16) * BPAD + ks + bColL) * 2);
                #pragma unroll
                for (int mf = 0; mf < 2; mf++)
                    #pragma unroll
                    for (int nf = 0; nf < 8; nf++)
                        mma_f16(acc[mf][nf], ah[mf],
                                bb[nf >> 1][(nf & 1) * 2], bb[nf >> 1][(nf & 1) * 2 + 1]);
            }
        }

        if (more) {
            pack_ls_f16(La, Lb, Ma, Mb, psum, psq, Ah);
            *(uint4*)(sm + K2_A(p1) + aSt) = make_uint4(Ah[0], Ah[1], Ah[2], Ah[3]);
            CP_WAIT0();
            __syncthreads();
        }
    }

    ((float*)(sm + K2_RS))[arow * 4 + (tid & 3)] = psum;
    ((float*)(sm + K2_RQ))[arow * 4 + (tid & 3)] = psq;
    __syncthreads();
    if (tid < K2BM) {
        const float* rs = (const float*)(sm + K2_RS) + tid * 4;
        const float* rq = (const float*)(sm + K2_RQ) + tid * 4;
        float ss = (rs[0] + rs[1]) + (rs[2] + rs[3]);
        float sq = (rq[0] + rq[1]) + (rq[2] + rq[3]);
        g_rowsum[ntBase + tid]   = ss;
        g_rowsumsq[ntBase + tid] = sq;
        ((float*)(sm + K2_RINV))[tid] = 1.f / (ss + 1.f);
    }
    __syncthreads();
    const float* rinv = (const float*)(sm + K2_RINV);

    #pragma unroll
    for (int mf = 0; mf < 2; mf++) {
        #pragma unroll
        for (int half = 0; half < 2; half++) {
            int row = warp_m * 32 + mf * 16 + half * 8 + (lane >> 2);
            int nt = ntBase + row;
            float inv = rinv[row];
            const float* fb = g_feat + (size_t)(nt >> 2) * F_;
            float* rb = g_recon   + (size_t)nt * F_;
            float* eb = g_edgefea + (size_t)nt * F_;
            #pragma unroll
            for (int nf = 0; nf < 8; nf++) {
                int col = warp_n * 64 + nf * 8 + (lane & 3) * 2;
                float d0 = acc[mf][nf][half * 2];
                float d1 = acc[mf][nf][half * 2 + 1];
                *(float2*)(rb + col) = make_float2(d0, d1);
                float2 fv = *(const float2*)(fb + col);
                *(float2*)(eb + col) = make_float2((d0 + fv.x) * inv, (d1 + fv.y) * inv);
            }
        }
    }
}

// ============================================================
// K_proj_all: merged bucketed projections, single-pass fp16.
// ============================================================
__global__ __launch_bounds__(256, 2) void k_proj_all()
{
    extern __shared__ char sm[];
    const uint32_t sb = smem_u32(sm);
    const int tid = threadIdx.x;
    const int wid = tid >> 5, lane = tid & 31;
    const int warp_m = wid & 1, warp_n = wid >> 1;

    const int t = blockIdx.x;
    const int cnt = g_tile_cnt[t];
    if (cnt == 0) return;
    const int s = g_tile_s[t];
    const int y = blockIdx.y;
    int mode, j = 0;
    if (y < 4)       { mode = 0; j = y; }
    else if (y == 4) { mode = 1; }
    else             { mode = 2; j = y - 5; }

    int* sidx = (int*)(sm + GIDX);
    const int start = g_tile_start[t];
    if (tid < 64) sidx[tid] = g_perm[start + min(tid, cnt - 1)];
    __syncthreads();

    const int arow = tid >> 2;
    const int akof = (tid & 3) * 8;
    const float* aptr;
    if (mode == 2) aptr = g_edgefea + ((size_t)sidx[arow] * T_ + j) * F_ + akof;
    else           aptr = g_feat + (size_t)sidx[arow] * F_ + akof;
    const uint32_t aSt = (uint32_t)(arow * APAD + akof) * 2;

    int z;
    if (mode == 0)      z = 1 + s * T_ + j;
    else if (mode == 1) z = 17 + s;
    else                z = 21 + s * T_ + j;
    const char* b_src = (const char*)(g_W16 + (size_t)z * F_ * F_ + (size_t)tid * F_);
    const uint32_t bSt = (uint32_t)(tid * BPAD) * 2;

    const int aRowL = warp_m * 32 + (lane & 7) + ((lane >> 3) & 1) * 8;
    const int aColL = (lane >> 4) * 8;
    const int bRowL = warp_n * 64 + (lane & 7) + ((lane >> 4) & 1) * 8;
    const int bColL = ((lane >> 3) & 1) * 8;

    uint32_t Ah[4];
    float4 Aa, Ab;

    Aa = ldg4(aptr); Ab = ldg4(aptr + 4);
    {
        uint32_t d = sb + GB(0) + bSt;
        #pragma unroll
        for (int q = 0; q < 4; q++) cpa16(d + q * 16, b_src + q * 16);
    }
    CP_COMMIT();
    pack_f16(Aa, Ab, Ah);
    *(uint4*)(sm + GA(0) + aSt) = make_uint4(Ah[0], Ah[1], Ah[2], Ah[3]);
    CP_WAIT0();
    __syncthreads();

    float acc[2][8][4];
    #pragma unroll
    for (int i = 0; i < 2; i++)
        #pragma unroll
        for (int q = 0; q < 8; q++)
            #pragma unroll
            for (int e = 0; e < 4; e++) acc[i][q][e] = 0.f;

    for (int c = 0; c < GKCH; c++) {
        const int st = c & 1;
        const bool more = (c + 1 < GKCH);
        if (more) {
            uint32_t d = sb + GB(st ^ 1) + bSt;
            const char* srcb = b_src + (size_t)(c + 1) * BK * 2;
            #pragma unroll
            for (int q = 0; q < 4; q++) cpa16(d + q * 16, srcb + q * 16);
            CP_COMMIT();
            Aa = ldg4(aptr + (c + 1) * BK);
            Ab = ldg4(aptr + (c + 1) * BK + 4);
        }

        const uint32_t aB = sb + GA(st);
        const uint32_t bB = sb + GB(st);

        #pragma unroll
        for (int ks = 0; ks < BK; ks += 16) {
            uint32_t ah[2][4], bb[4][4];
            ldm_x4(ah[0], aB + (uint32_t)((aRowL)      * APAD + ks + aColL) * 2);
            ldm_x4(ah[1], aB + (uint32_t)((aRowL + 16) * APAD + ks + aColL) * 2);
            #pragma unroll
            for (int g = 0; g < 4; g++)
                ldm_x4(bb[g], bB + (uint32_t)((bRowL + g * 16) * BPAD + ks + bColL) * 2);
            #pragma unroll
            for (int mf = 0; mf < 2; mf++)
                #pragma unroll
                for (int nf = 0; nf < 8; nf++)
                    mma_f16(acc[mf][nf], ah[mf],
                            bb[nf >> 1][(nf & 1) * 2], bb[nf >> 1][(nf & 1) * 2 + 1]);
        }

        if (more) {
            pack_f16(Aa, Ab, Ah);
            *(uint4*)(sm + GA(st^1) + aSt) = make_uint4(Ah[0], Ah[1], Ah[2], Ah[3]);
            CP_WAIT0();
            __syncthreads();
        }
    }

    if (mode == 0) {
        float* sred = (float*)(sm + GRED);
        #pragma unroll
        for (int mf = 0; mf < 2; mf++) {
            #pragma unroll
            for (int half = 0; half < 2; half++) {
                int row = warp_m * 32 + mf * 16 + half * 8 + (lane >> 2);
                int node = sidx[row];
                const float* rr = g_recon + ((size_t)node * T_ + j) * F_;
                float part = 0.f;
                #pragma unroll
                for (int nf = 0; nf < 8; nf++) {
                    int col = warp_n * 64 + nf * 8 + (lane & 3) * 2;
                    float2 rv = *(const float2*)(rr + col);
                    float d0 = acc[mf][nf][half * 2]     - rv.x;
                    float d1 = acc[mf][nf][half * 2 + 1] - rv.y;
                    part = fmaf(d0, d0, part);
                    part = fmaf(d1, d1, part);
                }
                part += __shfl_xor_sync(0xffffffffu, part, 1);
                part += __shfl_xor_sync(0xffffffffu, part, 2);
                if ((lane & 3) == 0) sred[row * 4 + warp_n] = part;
            }
        }
        __syncthreads();
        if (tid < 64) {
            const float* r4 = sred + tid * 4;
            float tot = (r4[0] + r4[1]) + (r4[2] + r4[3]);
            if (tid < cnt)
                g_rownorm[sidx[tid] * T_ + j] = sqrtf(tot);
        }
    } else {
        #pragma unroll
        for (int mf = 0; mf < 2; mf++) {
            #pragma unroll
            for (int half = 0; half < 2; half++) {
                int row = warp_m * 32 + mf * 16 + half * 8 + (lane >> 2);
                if (row >= cnt) continue;
                int node = sidx[row];
                float* ob;
                if (mode == 1) ob = g_nodeproj + (size_t)node * F_;
                else           ob = g_edgeproj + ((size_t)node * T_ + j) * F_;
                #pragma unroll
                for (int nf = 0; nf < 8; nf++) {
                    int col = warp_n * 64 + nf * 8 + (lane & 3) * 2;
                    *(float2*)(ob + col) = make_float2(acc[mf][nf][half * 2],
                                                       acc[mf][nf][half * 2 + 1]);
                }
            }
        }
    }
}

// ============================================================
// K_gemm3: g_feat = feature @ theta^T + bias; ALSO writes the
// fp16 transpose g_fT16 (fuses the old k_featT).
// ============================================================
__global__ __launch_bounds__(256, 2) void k_gemm3(const float* __restrict__ Ain,
                                                  const float* __restrict__ bias)
{
    extern __shared__ char sm[];
    const uint32_t sb = smem_u32(sm);
    const int tid = threadIdx.x;
    const int wid = tid >> 5, lane = tid & 31;
    const int warp_m = wid & 1, warp_n = wid >> 1;
    const int mBase = blockIdx.x * 64;

    const int arow = tid >> 2;
    const int akof = (tid & 3) * 8;
    const float* aptr = Ain + (size_t)(mBase + arow) * F_ + akof;
    const uint32_t aSt = (uint32_t)(arow * APAD + akof) * 2;

    const char* b_src = (const char*)(g_W16 + (size_t)tid * F_);
    const uint32_t bSt = (uint32_t)(tid * BPAD) * 2;

    const int aRowL = warp_m * 32 + (lane & 7) + ((lane >> 3) & 1) * 8;
    const int aColL = (lane >> 4) * 8;
    const int bRowL = warp_n * 64 + (lane & 7) + ((lane >> 4) & 1) * 8;
    const int bColL = ((lane >> 3) & 1) * 8;

    uint32_t Ah[4];
    float4 Aa, Ab;

    Aa = ldg4(aptr); Ab = ldg4(aptr + 4);
    {
        uint32_t d = sb + GB(0) + bSt;
        #pragma unroll
        for (int q = 0; q < 4; q++) cpa16(d + q * 16, b_src + q * 16);
    }
    CP_COMMIT();
    pack_f16(Aa, Ab, Ah);
    *(uint4*)(sm + GA(0) + aSt) = make_uint4(Ah[0], Ah[1], Ah[2], Ah[3]);
    CP_WAIT0();
    __syncthreads();

    float acc[2][8][4];
    #pragma unroll
    for (int i = 0; i < 2; i++)
        #pragma unroll
        for (int q = 0; q < 8; q++)
            #pragma unroll
            for (int e = 0; e < 4; e++) acc[i][q][e] = 0.f;

    for (int c = 0; c < GKCH; c++) {
        const int st = c & 1;
        const bool more = (c + 1 < GKCH);
        if (more) {
            uint32_t d = sb + GB(st ^ 1) + bSt;
            const char* srcb = b_src + (size_t)(c + 1) * BK * 2;
            #pragma unroll
            for (int q = 0; q < 4; q++) cpa16(d + q * 16, srcb + q * 16);
            CP_COMMIT();
            Aa = ldg4(aptr + (c + 1) * BK);
            Ab = ldg4(aptr + (c + 1) * BK + 4);
        }

        const uint32_t aB = sb + GA(st);
        const uint32_t bB = sb + GB(st);

        #pragma unroll
        for (int ks = 0; ks < BK; ks += 16) {
            uint32_t ah[2][4], bb[4][4];
            ldm_x4(ah[0], aB + (uint32_t)((aRowL)      * APAD + ks + aColL) * 2);
            ldm_x4(ah[1], aB + (uint32_t)((aRowL + 16) * APAD + ks + aColL) * 2);
            #pragma unroll
            for (int g = 0; g < 4; g++)
                ldm_x4(bb[g], bB + (uint32_t)((bRowL + g * 16) * BPAD + ks + bColL) * 2);
            #pragma unroll
            for (int mf = 0; mf < 2; mf++)
                #pragma unroll
                for (int nf = 0; nf < 8; nf++)
                    mma_f16(acc[mf][nf], ah[mf],
                            bb[nf >> 1][(nf & 1) * 2], bb[nf >> 1][(nf & 1) * 2 + 1]);
        }

        if (more) {
            pack_f16(Aa, Ab, Ah);
            *(uint4*)(sm + GA(st^1) + aSt) = make_uint4(Ah[0], Ah[1], Ah[2], Ah[3]);
            CP_WAIT0();
            __syncthreads();
        }
    }

    #pragma unroll
    for (int mf = 0; mf < 2; mf++) {
        #pragma unroll
        for (int half = 0; half < 2; half++) {
            int row = warp_m * 32 + mf * 16 + half * 8 + (lane >> 2);
            int grow = mBase + row;
            float* ob = g_feat + (size_t)grow * F_;
            #pragma unroll
            for (int nf = 0; nf < 8; nf++) {
                int col = warp_n * 64 + nf * 8 + (lane & 3) * 2;
                float v0 = acc[mf][nf][half * 2]     + bias[col];
                float v1 = acc[mf][nf][half * 2 + 1] + bias[col + 1];
                *(float2*)(ob + col) = make_float2(v0, v1);
                g_fT16[(size_t)col       * N_ + grow] = __float2half_rn(v0);
                g_fT16[(size_t)(col + 1) * N_ + grow] = __float2half_rn(v1);
            }
        }
    }
}

// ============================================================
// K_wconv: weights fp32 -> fp16
// ============================================================
__global__ __launch_bounds__(256) void k_wconv(const float* __restrict__ th,
                                               const float* __restrict__ rp,
                                               const float* __restrict__ np,
                                               const float* __restrict__ ep)
{
    int i4 = blockIdx.x * 256 + threadIdx.x;
    int i = i4 * 4;
    int z = i >> 16;
    int off = i & 65535;
    const float* src;
    if (z == 0)      src = th;
    else if (z < 17) src = rp + (size_t)(z - 1)  * 65536;
    else if (z < 21) src = np + (size_t)(z - 17) * 65536;
    else             src = ep + (size_t)(z - 21) * 65536;
    float4 v = ldg4(src + off);
    __half2 h0 = __floats2half2_rn(v.x, v.y);
    __half2 h1 = __floats2half2_rn(v.z, v.w);
    *(uint2*)(g_W16 + i) = make_uint2(*(uint32_t*)&h0, *(uint32_t*)&h1);
}

// ============================================================
// K_sort
// ============================================================
__global__ __launch_bounds__(256) void k_sort(const int* __restrict__ nmm)
{
    __shared__ int hist[4][256];
    __shared__ int basep[4][256];
    __shared__ int btot[4];
    __shared__ int boff[4];

    const int tid = threadIdx.x;
    const int r0 = tid * 16;
    int myb[16];
    int c[4] = {0, 0, 0, 0};
    #pragma unroll
    for (int i = 0; i < 16; i++) {
        int b = nmm[r0 + i];
        myb[i] = b;
        c[b]++;
    }
    #pragma unroll
    for (int b = 0; b < 4; b++) hist[b][tid] = c[b];
    __syncthreads();

    const int w = tid >> 5, lane = tid & 31;
    if (w < 4) {
        int b = w;
        int loc[8];
        int sum = 0;
        #pragma unroll
        for (int q = 0; q < 8; q++) {
            loc[q] = sum;
            sum += hist[b][lane * 8 + q];
        }
        int pre = sum;
        #pragma unroll
        for (int off = 1; off < 32; off <<= 1) {
            int v = __shfl_up_sync(0xffffffffu, pre, off);
            if (lane >= off) pre += v;
        }
        int tot = __shfl_sync(0xffffffffu, pre, 31);
        pre -= sum;
        #pragma unroll
        for (int q = 0; q < 8; q++) basep[b][lane * 8 + q] = pre + loc[q];
        if (lane == 31) btot[b] = tot;
    }
    __syncthreads();

    if (tid == 0) {
        int off = 0, t = 0;
        for (int b = 0; b < 4; b++) {
            boff[b] = off;
            int cnt = btot[b];
            for (int k = 0; k < cnt; k += 64) {
                g_tile_s[t] = b;
                g_tile_start[t] = off + k;
                g_tile_cnt[t] = min(64, cnt - k);
                t++;
            }
            off += cnt;
        }
        for (; t < MAXTILES; t++) { g_tile_cnt[t] = 0; g_tile_s[t] = 0; g_tile_start[t] = 0; }
    }
    __syncthreads();

    int pos[4];
    #pragma unroll
    for (int b = 0; b < 4; b++) pos[b] = boff[b] + basep[b][tid];
    #pragma unroll
    for (int i = 0; i < 16; i++) {
        int b = myb[i];
        g_perm[pos[b]++] = r0 + i;
    }
}

// ============================================================
// K_attn
// ============================================================
__global__ __launch_bounds__(256) void k_attn(float* __restrict__ node_rep)
{
    const int i = blockIdx.x, tid = threadIdx.x;
    const int h = tid >> 5, lane = tid & 31;
    __shared__ float sw[T_][H_];

    float np = g_nodeproj[(size_t)i * F_ + tid];
    const float inv = rsqrtf((float)D_);

    #pragma unroll
    for (int t = 0; t < T_; t++) {
        float v = np * g_edgeproj[((size_t)i * T_ + t) * F_ + tid];
        #pragma unroll
        for (int off = 16; off > 0; off >>= 1)
            v += __shfl_down_sync(0xffffffffu, v, off);
        if (lane == 0) sw[t][h] = v * inv;
    }
    __syncthreads();

    if (tid < T_) {
        int t = tid;
        float mx = sw[t][0];
        #pragma unroll
        for (int hh = 1; hh < H_; hh++) mx = fmaxf(mx, sw[t][hh]);
        float sm = 0.f;
        #pragma unroll
        for (int hh = 0; hh < H_; hh++) {
            float e = expf(sw[t][hh] - mx);
            sw[t][hh] = e;
            sm += e;
        }
        float r = 1.f / sm;
        #pragma unroll
        for (int hh = 0; hh < H_; hh++) sw[t][hh] *= r;
    }
    __syncthreads();

    float rep = 0.f;
    #pragma unroll
    for (int t = 0; t < T_; t++)
        rep += fmaxf(sw[t][h] * g_edgefea[((size_t)i * T_ + t) * F_ + tid], 0.f);
    node_rep[(size_t)i * F_ + tid] = rep;
}

// ============================================================
// K_tail: blocks 0..127 = prediction (8 warps, 1 p each);
//         block 128    = loss reduction.
// ============================================================
__global__ __launch_bounds__(256) void k_tail(const float* __restrict__ node_rep,
                                              const int* __restrict__ node_idx,
                                              const float* __restrict__ pw,
                                              const float* __restrict__ pb,
                                              float* __restrict__ predict,
                                              float* __restrict__ lossOut)
{
    if (blockIdx.x < 128) {
        const int warp = threadIdx.x >> 5, lane = threadIdx.x & 31;
        const int p = blockIdx.x * 8 + warp;
        const float* a = node_rep + (size_t)node_idx[p] * F_;

        float part[C_];
        #pragma unroll
        for (int c = 0; c < C_; c++) part[c] = 0.f;
        for (int f = lane; f < F_; f += 32) {
            float av = a[f];
            #pragma unroll
            for (int c = 0; c < C_; c++)
                part[c] = fmaf(av, pw[c * F_ + f], part[c]);
        }
        #pragma unroll
        for (int c = 0; c < C_; c++)
            #pragma unroll
            for (int off = 16; off > 0; off >>= 1)
                part[c] += __shfl_down_sync(0xffffffffu, part[c], off);

        if (lane == 0) {
            float sig[C_];
            float mx = -1e30f;
            #pragma unroll
            for (int c = 0; c < C_; c++) {
                float l = part[c] + pb[c];
                float sg = 1.f / (1.f + expf(-l));
                sig[c] = sg;
                mx = fmaxf(mx, sg);
            }
            float sm = 0.f;
            #pragma unroll
            for (int c = 0; c < C_; c++) {
                float e = expf(sig[c] - mx);
                sig[c] = e;
                sm += e;
            }
            float r = 1.f / sm;
            #pragma unroll
            for (int c = 0; c < C_; c++)
                predict[(size_t)p * C_ + c] = sig[c] * r;
        }
    } else {
        __shared__ float s1[256], s2[256], s3[256];
        int tid = threadIdx.x;
        float l1 = 0.f, l2 = 0.f, re = 0.f;
        for (int i = tid; i < NT_; i += 256) {
            l1 += g_rowsum[i];
            l2 += sqrtf(g_rowsumsq[i]);
            re += g_rownorm[i];
        }
        s1[tid] = l1; s2[tid] = l2; s3[tid] = re;
        __syncthreads();
        for (int off = 128; off > 0; off >>= 1) {
            if (tid < off) {
                s1[tid] += s1[tid + off];
                s2[tid] += s2[tid + off];
                s3[tid] += s3[tid + off];
            }
            __syncthreads();
        }
        if (tid == 0)
            lossOut[0] = 0.1f * (0.01f * s3[0] + 0.2f * s2[0] + s1[0]);
    }
}

// ============================================================
extern "C" void kernel_launch(void* const* d_in, const int* in_sizes, int n_in,
                              void* d_out, int out_size)
{
    (void)in_sizes; (void)n_in; (void)out_size;
    const float* feature  = (const float*)d_in[0];
    const float* mask     = (const float*)d_in[1];
    const int*   nmm      = (const int*)  d_in[2];
    const int*   node_idx = (const int*)  d_in[3];
    const float* theta_w  = (const float*)d_in[4];
    const float* theta_b  = (const float*)d_in[5];
    const float* linear   = (const float*)d_in[6];
    const float* rp       = (const float*)d_in[7];
    const float* mhnp     = (const float*)d_in[8];
    const float* mhep     = (const float*)d_in[9];
    const float* pw       = (const float*)d_in[10];
    const float* pb       = (const float*)d_in[11];

    float* out      = (float*)d_out;
    float* predict  = out;
    float* loss     = out + P_ * C_;
    float* node_rep = out + P_ * C_ + 1;

    cudaFuncSetAttribute(k2_mma,     cudaFuncAttributeMaxDynamicSharedMemorySize, SMEM_K2);
    cudaFuncSetAttribute(k_proj_all, cudaFuncAttributeMaxDynamicSharedMemorySize, SMEM_G);
    cudaFuncSetAttribute(k_gemm3,    cudaFuncAttributeMaxDynamicSharedMemorySize, SMEM_G);

    // k2 placed 4th => lands in the profiled slot
    k_wconv<<<37 * 65536 / 1024, 256>>>(theta_w, rp, mhnp, mhep);
    k_gemm3<<<N_ / 64, 256, SMEM_G>>>(feature, theta_b);
    k_sort<<<1, 256>>>(nmm);
    k2_mma<<<NT_ / K2BM, 512, SMEM_K2>>>(linear, mask);
    k_proj_all<<<dim3(MAXTILES, 9), 256, SMEM_G>>>();
    k_attn<<<N_, 256>>>(node_rep);
    k_tail<<<129, 256>>>(node_rep, node_idx, pw, pb, predict, loss);
}